// round 5
// baseline (speedup 1.0000x reference)
#include <cuda_runtime.h>
#include <math.h>

#define B 8
#define NPIX 256
#define M 8192
#define NCP 24576
#define NCA 24576
#define FEPS 1e-16f

#define TM 32
#define KC 16
#define KFOLD 128   // folded K dimension (c = 1..128)

#define OFF_VIS 0
#define OFF_VISAMP (B*2*M)
#define OFF_CPHASE (OFF_VISAMP + B*M)
#define OFF_LOGCAMP (OFF_CPHASE + B*NCP)

// ---- device scratch (no allocation allowed) ----
__device__ float g_cosV[KFOLD*M];   // [c][m], c index 0..127 == cc-1, coalesced in m
__device__ float g_sinV[KFOLD*M];
__device__ float g_EuR[M*NPIX];     // [m][x] : cos(ku*x)
__device__ float g_EuI[M*NPIX];     // [m][x] : -sin(ku*x)
__device__ float g_P[B*KFOLD*NPIX]; // folded even image
__device__ float g_Q[B*KFOLD*NPIX]; // folded odd image
__device__ float g_visR[B*M];
__device__ float g_visI[B*M];

// ---------------------------------------------------------------------------
// Kernel 1a: trig tables.
//   cosV/sinV: cc = c+1 in [1,128], angle = kv[m]*cc    (half-size via fold)
//   Eu:        full 256-pt row, Eu = exp(-i*ku*(x-128))
// ---------------------------------------------------------------------------
__global__ void trig_kernel(const float* __restrict__ ktraj) {
    int idx = blockIdx.x * blockDim.x + threadIdx.x;
    if (idx < KFOLD * M) {               // idx = c*M + m
        int m = idx & (M - 1);
        int c = idx >> 13;               // / M
        float cc = (float)(c + 1);
        float s, co;
        sincosf(ktraj[m] * cc, &s, &co); // kv row
        g_cosV[idx] = co;
        g_sinV[idx] = s;
    }
    if (idx < M * NPIX) {                // idx = m*NPIX + x
        int x = idx & (NPIX - 1);
        int m = idx >> 8;                // / NPIX
        float cx = (float)(x - NPIX / 2);
        float s, co;
        sincosf(ktraj[M + m] * cx, &s, &co);  // ku row
        g_EuR[idx] = co;
        g_EuI[idx] = -s;
    }
}

// ---------------------------------------------------------------------------
// Kernel 1b: fold image over y.  c index 0..127 means cc = c+1.
//   cc in [1,127]: P = img[128+cc] + img[128-cc],  Q = img[128+cc] - img[128-cc]
//   cc == 128:     P = img[0],                     Q = -img[0]
// ---------------------------------------------------------------------------
__global__ void fold_kernel(const float* __restrict__ img) {
    int idx = blockIdx.x * blockDim.x + threadIdx.x;
    if (idx >= B * KFOLD * NPIX) return;
    int x = idx & (NPIX - 1);
    int t = idx >> 8;
    int c = t & (KFOLD - 1);
    int b = t >> 7;
    int cc = c + 1;
    const float* im = img + (size_t)b * NPIX * NPIX;
    float p, q;
    if (cc < 128) {
        float hi = im[(128 + cc) * NPIX + x];
        float lo = im[(128 - cc) * NPIX + x];
        p = hi + lo;
        q = hi - lo;
    } else {
        float v = im[x];     // y = 0 row
        p = v;
        q = -v;
    }
    g_P[idx] = p;
    g_Q[idx] = q;
}

// ---------------------------------------------------------------------------
// Kernel 2: heavy stage (folded).  CTA = (32 m, one b).
//   cospart[m,x] = img[b,128,x] + sum_c cosV[c][m] * P[b,c,x]
//   sinpart[m,x] =                sum_c sinV[c][m] * Q[b,c,x]
//   t = cospart - i*sinpart ; then contract over x with Eu, apply pulsefac.
// Threads: 256. warp = m-group (4 m), lane = x-group (8 x).
// ---------------------------------------------------------------------------
__global__ __launch_bounds__(256, 2) void dft_kernel(
    const float* __restrict__ img,
    const float* __restrict__ pulsefac,
    float* __restrict__ out)
{
    __shared__ float sAc[KC][TM];
    __shared__ float sAs[KC][TM];
    __shared__ float sP[KC][NPIX];
    __shared__ float sQ[KC][NPIX];

    const int b    = blockIdx.y;
    const int m0   = blockIdx.x * TM;
    const int tid  = threadIdx.x;
    const int lane = tid & 31;   // x = lane*8 + j
    const int warp = tid >> 5;   // m = m0 + warp*4 + i

    float accr[4][8], acci[4][8];
    #pragma unroll
    for (int i = 0; i < 4; ++i)
        #pragma unroll
        for (int j = 0; j < 8; ++j) { accr[i][j] = 0.f; acci[i][j] = 0.f; }

    for (int c0 = 0; c0 < KFOLD; c0 += KC) {
        __syncthreads();
        // A tiles: cos/sin [c0..c0+KC) x [m0..m0+TM), coalesced in m
        #pragma unroll
        for (int t = tid; t < KC * TM; t += 256) {
            int k  = t >> 5;          // TM == 32
            int mm = t & 31;
            sAc[k][mm] = g_cosV[(c0 + k) * M + m0 + mm];
            sAs[k][mm] = g_sinV[(c0 + k) * M + m0 + mm];
        }
        // B tiles: folded P/Q rows (vectorized, coalesced)
        {
            const float4* srcP = (const float4*)(g_P + ((size_t)b * KFOLD + c0) * NPIX);
            const float4* srcQ = (const float4*)(g_Q + ((size_t)b * KFOLD + c0) * NPIX);
            float4* dstP = (float4*)(&sP[0][0]);
            float4* dstQ = (float4*)(&sQ[0][0]);
            #pragma unroll
            for (int t = tid; t < KC * NPIX / 4; t += 256) {
                dstP[t] = srcP[t];
                dstQ[t] = srcQ[t];
            }
        }
        __syncthreads();

        #pragma unroll
        for (int k = 0; k < KC; ++k) {
            float4 acv = *(const float4*)&sAc[k][warp * 4];   // warp-broadcast
            float4 asv = *(const float4*)&sAs[k][warp * 4];
            float4 p0  = *(const float4*)&sP[k][lane * 8];
            float4 p1  = *(const float4*)&sP[k][lane * 8 + 4];
            float4 q0  = *(const float4*)&sQ[k][lane * 8];
            float4 q1  = *(const float4*)&sQ[k][lane * 8 + 4];
            float ac[4] = {acv.x, acv.y, acv.z, acv.w};
            float as[4] = {asv.x, asv.y, asv.z, asv.w};
            float pv[8] = {p0.x, p0.y, p0.z, p0.w, p1.x, p1.y, p1.z, p1.w};
            float qv[8] = {q0.x, q0.y, q0.z, q0.w, q1.x, q1.y, q1.z, q1.w};
            #pragma unroll
            for (int i = 0; i < 4; ++i)
                #pragma unroll
                for (int j = 0; j < 8; ++j) {
                    accr[i][j] = fmaf(ac[i], pv[j], accr[i][j]);
                    acci[i][j] = fmaf(as[i], qv[j], acci[i][j]);
                }
        }
    }

    // Add the c==0 (y==128) row: same for all m.
    {
        const float4* rp = (const float4*)(img + ((size_t)b * NPIX + 128) * NPIX + lane * 8);
        float4 r0 = rp[0], r1 = rp[1];
        float rowv[8] = {r0.x, r0.y, r0.z, r0.w, r1.x, r1.y, r1.z, r1.w};
        #pragma unroll
        for (int i = 0; i < 4; ++i)
            #pragma unroll
            for (int j = 0; j < 8; ++j)
                accr[i][j] += rowv[j];
    }

    // Epilogue: t = accr - i*acci ; contract over x with Eu = er + i*ei.
    //   real: accr*er + acci*ei      imag: accr*ei - acci*er
    float pr[4] = {0.f, 0.f, 0.f, 0.f};
    float pim[4] = {0.f, 0.f, 0.f, 0.f};
    #pragma unroll
    for (int i = 0; i < 4; ++i) {
        int m = m0 + warp * 4 + i;
        const float4* eur = (const float4*)(g_EuR + (size_t)m * NPIX + lane * 8);
        const float4* eui = (const float4*)(g_EuI + (size_t)m * NPIX + lane * 8);
        float4 er0 = eur[0], er1 = eur[1];
        float4 ei0 = eui[0], ei1 = eui[1];
        float er[8] = {er0.x, er0.y, er0.z, er0.w, er1.x, er1.y, er1.z, er1.w};
        float ei[8] = {ei0.x, ei0.y, ei0.z, ei0.w, ei1.x, ei1.y, ei1.z, ei1.w};
        #pragma unroll
        for (int j = 0; j < 8; ++j) {
            pr[i]  = fmaf(accr[i][j], er[j], fmaf( acci[i][j], ei[j], pr[i]));
            pim[i] = fmaf(accr[i][j], ei[j], fmaf(-acci[i][j], er[j], pim[i]));
        }
    }
    #pragma unroll
    for (int off = 16; off > 0; off >>= 1) {
        #pragma unroll
        for (int i = 0; i < 4; ++i) {
            pr[i]  += __shfl_xor_sync(0xffffffffu, pr[i], off);
            pim[i] += __shfl_xor_sync(0xffffffffu, pim[i], off);
        }
    }
    if (lane == 0) {
        #pragma unroll
        for (int i = 0; i < 4; ++i) {
            int m = m0 + warp * 4 + i;
            float p0 = pulsefac[m];
            float p1 = pulsefac[M + m];
            float re = pr[i] * p0 - pim[i] * p1;
            float im = pr[i] * p1 + pim[i] * p0;
            out[OFF_VIS + (b * 2) * M + m]     = re;
            out[OFF_VIS + (b * 2 + 1) * M + m] = im;
            out[OFF_VISAMP + b * M + m] = sqrtf(re * re + im * im + FEPS);
            g_visR[b * M + m] = re;
            g_visI[b * M + m] = im;
        }
    }
}

// ---------------------------------------------------------------------------
// Kernel 3: closure phases
// ---------------------------------------------------------------------------
__global__ void cphase_kernel(const float* __restrict__ sign,
                              const int* __restrict__ ind,
                              float* __restrict__ out) {
    int idx = blockIdx.x * blockDim.x + threadIdx.x;
    if (idx >= B * NCP) return;
    int b = idx / NCP;
    int n = idx - b * NCP;
    float s = 0.f;
    #pragma unroll
    for (int k = 0; k < 3; ++k) {
        int id   = ind[k * NCP + n];
        float sg = sign[k * NCP + n];
        float re = g_visR[b * M + id];
        float im = g_visI[b * M + id];
        s += sg * atan2f(im, re);
    }
    out[OFF_CPHASE + idx] = s * 57.29577951308232f;  // 180/pi
}

// ---------------------------------------------------------------------------
// Kernel 4: log closure amplitudes
// ---------------------------------------------------------------------------
__global__ void logcamp_kernel(const int* __restrict__ ind,
                               float* __restrict__ out) {
    int idx = blockIdx.x * blockDim.x + threadIdx.x;
    if (idx >= B * NCA) return;
    int b = idx / NCA;
    int n = idx - b * NCA;
    float la[4];
    #pragma unroll
    for (int k = 0; k < 4; ++k) {
        int id   = ind[k * NCA + n];
        float re = g_visR[b * M + id];
        float im = g_visI[b * M + id];
        la[k] = 0.5f * logf(re * re + im * im + FEPS);  // log(sqrt) = 0.5*log
    }
    out[OFF_LOGCAMP + idx] = la[0] + la[1] - la[2] - la[3];
}

extern "C" void kernel_launch(void* const* d_in, const int* in_sizes, int n_in,
                              void* d_out, int out_size) {
    const float* images      = (const float*)d_in[0];
    const float* ktraj       = (const float*)d_in[1];
    const float* pulsefac    = (const float*)d_in[2];
    const float* cphase_sign = (const float*)d_in[3];
    const int*   cphase_ind  = (const int*)d_in[4];
    const int*   camp_ind    = (const int*)d_in[5];
    float* out = (float*)d_out;

    trig_kernel<<<(M * NPIX) / 256, 256>>>(ktraj);           // covers both tables
    fold_kernel<<<(B * KFOLD * NPIX) / 256, 256>>>(images);

    dim3 grid(M / TM, B);
    dft_kernel<<<grid, 256>>>(images, pulsefac, out);

    cphase_kernel<<<(B * NCP + 255) / 256, 256>>>(cphase_sign, cphase_ind, out);
    logcamp_kernel<<<(B * NCA + 255) / 256, 256>>>(camp_ind, out);
}

// round 7
// speedup vs baseline: 2.3648x; 2.3648x over previous
#include <cuda_runtime.h>
#include <cuda_bf16.h>
#include <cstdint>
#include <math.h>

#define B 8
#define NPIX 256
#define M 8192
#define NCP 24576
#define NCA 24576
#define FEPS 1e-16f
#define KFOLD 128
#define MTILE 64

#define OFF_VIS 0
#define OFF_VISAMP (B*2*M)
#define OFF_CPHASE (OFF_VISAMP + B*M)
#define OFF_LOGCAMP (OFF_CPHASE + B*NCP)

// ---- device scratch (no allocation allowed) ----
__device__ __nv_bfloat16 g_cosHi[M*KFOLD];    // [m][c], c fastest
__device__ __nv_bfloat16 g_cosLo[M*KFOLD];
__device__ __nv_bfloat16 g_sinHi[M*KFOLD];
__device__ __nv_bfloat16 g_sinLo[M*KFOLD];
__device__ float2        g_Eu[M*NPIX];        // [m][x]  (er, ei)
__device__ __nv_bfloat16 g_PHi[B*NPIX*KFOLD]; // [b][x][c], c fastest
__device__ __nv_bfloat16 g_PLo[B*NPIX*KFOLD];
__device__ __nv_bfloat16 g_QHi[B*NPIX*KFOLD];
__device__ __nv_bfloat16 g_QLo[B*NPIX*KFOLD];
__device__ float g_visR[B*M];
__device__ float g_visI[B*M];

// ---------------------------------------------------------------------------
// m16n8k16 bf16 mma (baseline PTX, no arch-suffix gating -> ok on sm_103)
// A row-major m x k ([m][c]); B col-major k x n, i.e. memory [x][c] K-major.
// ---------------------------------------------------------------------------
__device__ __forceinline__ void mma16816(float* d, const uint32_t* a, const uint32_t* b) {
    asm volatile(
        "mma.sync.aligned.m16n8k16.row.col.f32.bf16.bf16.f32 "
        "{%0,%1,%2,%3}, {%4,%5,%6,%7}, {%8,%9}, {%0,%1,%2,%3};"
        : "+f"(d[0]), "+f"(d[1]), "+f"(d[2]), "+f"(d[3])
        : "r"(a[0]), "r"(a[1]), "r"(a[2]), "r"(a[3]), "r"(b[0]), "r"(b[1]));
}

// ---------------- SMEM layout ----------------
// APAD = 40 bf16 (80 bytes) row stride: conflict-free fragment LDS
#define APAD_B   80
#define A_ARR_B  (64 * APAD_B)      // 5120
#define B_ARR_B  (256 * APAD_B)     // 20480
#define SM_A(arr)   ((arr) * A_ARR_B)
#define SM_B(arr)   (4 * A_ARR_B + (arr) * B_ARR_B)
#define SM_IMG      (4 * A_ARR_B + 4 * B_ARR_B)          // 102400, 256 floats
#define SM_REDR     (SM_IMG + 1024)                      // 8*64 floats
#define SM_REDI     (SM_REDR + 2048)
#define SM_TOTAL    (SM_REDI + 2048)                     // 107520

// ---------------------------------------------------------------------------
// Kernel 1: trig tables (bf16 split cos/sin; fp32 float2 Eu [m][x])
// ---------------------------------------------------------------------------
__global__ void trig_kernel(const float* __restrict__ ktraj) {
    int idx = blockIdx.x * blockDim.x + threadIdx.x;
    if (idx < M * KFOLD) {            // [m][c], c fastest
        int c = idx & (KFOLD - 1);
        int m = idx >> 7;
        float s, co;
        sincosf(ktraj[m] * (float)(c + 1), &s, &co);
        __nv_bfloat16 ch = __float2bfloat16(co);
        __nv_bfloat16 sh = __float2bfloat16(s);
        g_cosHi[idx] = ch;
        g_cosLo[idx] = __float2bfloat16(co - __bfloat162float(ch));
        g_sinHi[idx] = sh;
        g_sinLo[idx] = __float2bfloat16(s - __bfloat162float(sh));
    }
    if (idx < M * NPIX) {             // [m][x], x fastest
        int x = idx & (NPIX - 1);
        int m = idx >> 8;
        float cx = (float)(x - NPIX / 2);
        float s, co;
        sincosf(ktraj[M + m] * cx, &s, &co);
        g_Eu[idx] = make_float2(co, -s);
    }
}

// ---------------------------------------------------------------------------
// Kernel 1b: fold image, bf16 split, layout [b][x][c]
// ---------------------------------------------------------------------------
__global__ void fold_kernel(const float* __restrict__ img) {
    int idx = blockIdx.x * blockDim.x + threadIdx.x;
    if (idx >= B * NPIX * KFOLD) return;
    int c = idx & (KFOLD - 1);
    int x = (idx >> 7) & (NPIX - 1);
    int b = idx >> 15;
    int cc = c + 1;
    const float* im = img + (size_t)b * NPIX * NPIX;
    float p, q;
    if (cc < 128) {
        float hi = im[(128 + cc) * NPIX + x];
        float lo = im[(128 - cc) * NPIX + x];
        p = hi + lo; q = hi - lo;
    } else {
        float v = im[x];
        p = v; q = -v;
    }
    __nv_bfloat16 ph = __float2bfloat16(p);
    __nv_bfloat16 qh = __float2bfloat16(q);
    g_PHi[idx] = ph;
    g_PLo[idx] = __float2bfloat16(p - __bfloat162float(ph));
    g_QHi[idx] = qh;
    g_QLo[idx] = __float2bfloat16(q - __bfloat162float(qh));
}

// ---------------------------------------------------------------------------
// Kernel 2: HMMA stage.  CTA = (64 m, one b), 8 warps; warp w owns
// x in [32w, 32w+32).  Split GEMM: acc = Hi*Hi + Hi*Lo + Lo*Hi for
// (cos,P)->accR and (sin,Q)->accI.  Epilogue contracts x with Eu in regs.
// ---------------------------------------------------------------------------
__global__ __launch_bounds__(256, 1) void dft_mma_kernel(
    const float* __restrict__ img,
    const float* __restrict__ pulsefac,
    float* __restrict__ out)
{
    extern __shared__ char sm[];

    const int b    = blockIdx.y;
    const int m0   = blockIdx.x * MTILE;
    const int tid  = threadIdx.x;
    const int warp = tid >> 5;
    const int lane = tid & 31;
    const int r    = lane >> 2;      // fragment row group 0..7
    const int cp   = lane & 3;       // fragment col pair 0..3
    const int wx   = warp * 32;      // this warp's x base

    // accum: [tm][tx][4]  (tm: 4 x 16m, tx: 4 x 8x)
    float accR[4][4][4], accI[4][4][4];
    #pragma unroll
    for (int i = 0; i < 4; ++i)
        #pragma unroll
        for (int j = 0; j < 4; ++j)
            #pragma unroll
            for (int k = 0; k < 4; ++k) { accR[i][j][k] = 0.f; accI[i][j][k] = 0.f; }

    // stage img center row (y = 128)
    ((float*)(sm + SM_IMG))[tid] = img[((size_t)b * NPIX + 128) * NPIX + tid];

    const __nv_bfloat16* gA[4] = {g_cosHi, g_cosLo, g_sinHi, g_sinLo};
    const __nv_bfloat16* gB[4] = {g_PHi, g_PLo, g_QHi, g_QLo};

    for (int chunk = 0; chunk < 4; ++chunk) {
        const int c0 = chunk * 32;
        __syncthreads();
        // stage A: 4 arrays x 64 rows x 8 uint2 (64B of K per row)
        #pragma unroll
        for (int t = tid; t < 2048; t += 256) {
            int arr = t >> 9, rem = t & 511, row = rem >> 3, seg = rem & 7;
            uint2 v = *(const uint2*)(gA[arr] + ((size_t)(m0 + row)) * KFOLD + c0 + seg * 4);
            *(uint2*)(sm + SM_A(arr) + row * APAD_B + seg * 8) = v;
        }
        // stage B: 4 arrays x 256 rows x 8 uint2
        #pragma unroll
        for (int t = tid; t < 8192; t += 256) {
            int arr = t >> 11, rem = t & 2047, row = rem >> 3, seg = rem & 7;
            uint2 v = *(const uint2*)(gB[arr] + ((size_t)(b * NPIX + row)) * KFOLD + c0 + seg * 4);
            *(uint2*)(sm + SM_B(arr) + row * APAD_B + seg * 8) = v;
        }
        __syncthreads();

        #pragma unroll
        for (int ks = 0; ks < 2; ++ks) {
            const int kb = ks * 32 + cp * 4;   // byte offset within row
            uint32_t aH[4][4], aL[4][4], bH[4][2], bL[4][2];

            // ---- real part: cos x P ----
            #pragma unroll
            for (int tm = 0; tm < 4; ++tm) {
                const char* pH = sm + SM_A(0) + (tm * 16 + r) * APAD_B + kb;
                const char* pL = sm + SM_A(1) + (tm * 16 + r) * APAD_B + kb;
                aH[tm][0] = *(const uint32_t*)(pH);
                aH[tm][1] = *(const uint32_t*)(pH + 8 * APAD_B);
                aH[tm][2] = *(const uint32_t*)(pH + 16);
                aH[tm][3] = *(const uint32_t*)(pH + 8 * APAD_B + 16);
                aL[tm][0] = *(const uint32_t*)(pL);
                aL[tm][1] = *(const uint32_t*)(pL + 8 * APAD_B);
                aL[tm][2] = *(const uint32_t*)(pL + 16);
                aL[tm][3] = *(const uint32_t*)(pL + 8 * APAD_B + 16);
            }
            #pragma unroll
            for (int tx = 0; tx < 4; ++tx) {
                const char* pH = sm + SM_B(0) + (wx + tx * 8 + r) * APAD_B + kb;
                const char* pL = sm + SM_B(1) + (wx + tx * 8 + r) * APAD_B + kb;
                bH[tx][0] = *(const uint32_t*)(pH);
                bH[tx][1] = *(const uint32_t*)(pH + 16);
                bL[tx][0] = *(const uint32_t*)(pL);
                bL[tx][1] = *(const uint32_t*)(pL + 16);
            }
            #pragma unroll
            for (int tm = 0; tm < 4; ++tm)
                #pragma unroll
                for (int tx = 0; tx < 4; ++tx) {
                    mma16816(accR[tm][tx], aH[tm], bH[tx]);
                    mma16816(accR[tm][tx], aH[tm], bL[tx]);
                    mma16816(accR[tm][tx], aL[tm], bH[tx]);
                }

            // ---- imag part: sin x Q ----
            #pragma unroll
            for (int tm = 0; tm < 4; ++tm) {
                const char* pH = sm + SM_A(2) + (tm * 16 + r) * APAD_B + kb;
                const char* pL = sm + SM_A(3) + (tm * 16 + r) * APAD_B + kb;
                aH[tm][0] = *(const uint32_t*)(pH);
                aH[tm][1] = *(const uint32_t*)(pH + 8 * APAD_B);
                aH[tm][2] = *(const uint32_t*)(pH + 16);
                aH[tm][3] = *(const uint32_t*)(pH + 8 * APAD_B + 16);
                aL[tm][0] = *(const uint32_t*)(pL);
                aL[tm][1] = *(const uint32_t*)(pL + 8 * APAD_B);
                aL[tm][2] = *(const uint32_t*)(pL + 16);
                aL[tm][3] = *(const uint32_t*)(pL + 8 * APAD_B + 16);
            }
            #pragma unroll
            for (int tx = 0; tx < 4; ++tx) {
                const char* pH = sm + SM_B(2) + (wx + tx * 8 + r) * APAD_B + kb;
                const char* pL = sm + SM_B(3) + (wx + tx * 8 + r) * APAD_B + kb;
                bH[tx][0] = *(const uint32_t*)(pH);
                bH[tx][1] = *(const uint32_t*)(pH + 16);
                bL[tx][0] = *(const uint32_t*)(pL);
                bL[tx][1] = *(const uint32_t*)(pL + 16);
            }
            #pragma unroll
            for (int tm = 0; tm < 4; ++tm)
                #pragma unroll
                for (int tx = 0; tx < 4; ++tx) {
                    mma16816(accI[tm][tx], aH[tm], bH[tx]);
                    mma16816(accI[tm][tx], aH[tm], bL[tx]);
                    mma16816(accI[tm][tx], aL[tm], bH[tx]);
                }
        }
    }

    // ---- epilogue: T = accR - i*accI (+ center row), contract x with Eu ----
    const float* s_img = (const float*)(sm + SM_IMG);
    float pr[4][2], pim[4][2];
    #pragma unroll
    for (int tm = 0; tm < 4; ++tm)
        #pragma unroll
        for (int h = 0; h < 2; ++h) { pr[tm][h] = 0.f; pim[tm][h] = 0.f; }

    #pragma unroll
    for (int tm = 0; tm < 4; ++tm)
        #pragma unroll
        for (int h = 0; h < 2; ++h) {
            int m = tm * 16 + r + h * 8;
            #pragma unroll
            for (int tx = 0; tx < 4; ++tx) {
                int x = wx + tx * 8 + cp * 2;
                float4 e = *(const float4*)(g_Eu + (size_t)(m0 + m) * NPIX + x); // er0,ei0,er1,ei1
                float tR0 = accR[tm][tx][h * 2 + 0] + s_img[x];
                float tR1 = accR[tm][tx][h * 2 + 1] + s_img[x + 1];
                float tI0 = accI[tm][tx][h * 2 + 0];
                float tI1 = accI[tm][tx][h * 2 + 1];
                pr[tm][h]  = fmaf(tR0, e.x, fmaf(tI0, e.y, fmaf(tR1, e.z, fmaf(tI1, e.w, pr[tm][h]))));
                pim[tm][h] = fmaf(tR0, e.y, fmaf(-tI0, e.x, fmaf(tR1, e.w, fmaf(-tI1, e.z, pim[tm][h]))));
            }
        }
    // quad reduce (lanes sharing the same m differ only in cp)
    #pragma unroll
    for (int tm = 0; tm < 4; ++tm)
        #pragma unroll
        for (int h = 0; h < 2; ++h) {
            pr[tm][h]  += __shfl_xor_sync(0xffffffffu, pr[tm][h], 1);
            pr[tm][h]  += __shfl_xor_sync(0xffffffffu, pr[tm][h], 2);
            pim[tm][h] += __shfl_xor_sync(0xffffffffu, pim[tm][h], 1);
            pim[tm][h] += __shfl_xor_sync(0xffffffffu, pim[tm][h], 2);
        }
    float* sredR = (float*)(sm + SM_REDR);
    float* sredI = (float*)(sm + SM_REDI);
    if (cp == 0) {
        #pragma unroll
        for (int tm = 0; tm < 4; ++tm)
            #pragma unroll
            for (int h = 0; h < 2; ++h) {
                int ml = tm * 16 + r + h * 8;
                sredR[warp * 64 + ml] = pr[tm][h];
                sredI[warp * 64 + ml] = pim[tm][h];
            }
    }
    __syncthreads();

    if (tid < 64) {
        float PR = 0.f, PIM = 0.f;
        #pragma unroll
        for (int w = 0; w < 8; ++w) { PR += sredR[w * 64 + tid]; PIM += sredI[w * 64 + tid]; }
        int m = m0 + tid;
        float p0 = pulsefac[m];
        float p1 = pulsefac[M + m];
        float re = PR * p0 - PIM * p1;
        float im = PR * p1 + PIM * p0;
        out[OFF_VIS + (b * 2) * M + m]     = re;
        out[OFF_VIS + (b * 2 + 1) * M + m] = im;
        out[OFF_VISAMP + b * M + m] = sqrtf(re * re + im * im + FEPS);
        g_visR[b * M + m] = re;
        g_visI[b * M + m] = im;
    }
}

// ---------------------------------------------------------------------------
// Kernel 3: closure phases
// ---------------------------------------------------------------------------
__global__ void cphase_kernel(const float* __restrict__ sign,
                              const int* __restrict__ ind,
                              float* __restrict__ out) {
    int idx = blockIdx.x * blockDim.x + threadIdx.x;
    if (idx >= B * NCP) return;
    int b = idx / NCP;
    int n = idx - b * NCP;
    float s = 0.f;
    #pragma unroll
    for (int k = 0; k < 3; ++k) {
        int id   = ind[k * NCP + n];
        float sg = sign[k * NCP + n];
        s += sg * atan2f(g_visI[b * M + id], g_visR[b * M + id]);
    }
    out[OFF_CPHASE + idx] = s * 57.29577951308232f;
}

// ---------------------------------------------------------------------------
// Kernel 4: log closure amplitudes
// ---------------------------------------------------------------------------
__global__ void logcamp_kernel(const int* __restrict__ ind,
                               float* __restrict__ out) {
    int idx = blockIdx.x * blockDim.x + threadIdx.x;
    if (idx >= B * NCA) return;
    int b = idx / NCA;
    int n = idx - b * NCA;
    float la[4];
    #pragma unroll
    for (int k = 0; k < 4; ++k) {
        int id   = ind[k * NCA + n];
        float re = g_visR[b * M + id];
        float im = g_visI[b * M + id];
        la[k] = 0.5f * logf(re * re + im * im + FEPS);
    }
    out[OFF_LOGCAMP + idx] = la[0] + la[1] - la[2] - la[3];
}

extern "C" void kernel_launch(void* const* d_in, const int* in_sizes, int n_in,
                              void* d_out, int out_size) {
    const float* images      = (const float*)d_in[0];
    const float* ktraj       = (const float*)d_in[1];
    const float* pulsefac    = (const float*)d_in[2];
    const float* cphase_sign = (const float*)d_in[3];
    const int*   cphase_ind  = (const int*)d_in[4];
    const int*   camp_ind    = (const int*)d_in[5];
    float* out = (float*)d_out;

    cudaFuncSetAttribute(dft_mma_kernel, cudaFuncAttributeMaxDynamicSharedMemorySize, SM_TOTAL);

    trig_kernel<<<(M * NPIX) / 256, 256>>>(ktraj);
    fold_kernel<<<(B * NPIX * KFOLD) / 256, 256>>>(images);

    dim3 grid(M / MTILE, B);
    dft_mma_kernel<<<grid, 256, SM_TOTAL>>>(images, pulsefac, out);

    cphase_kernel<<<(B * NCP + 255) / 256, 256>>>(cphase_sign, cphase_ind, out);
    logcamp_kernel<<<(B * NCA + 255) / 256, 256>>>(camp_ind, out);
}

// round 8
// speedup vs baseline: 2.4825x; 1.0498x over previous
#include <cuda_runtime.h>
#include <cuda_bf16.h>
#include <cstdint>
#include <math.h>

#define B 8
#define NPIX 256
#define M 8192
#define NCP 24576
#define NCA 24576
#define FEPS 1e-16f
#define KFOLD 128
#define MTILE 64

#define OFF_VIS 0
#define OFF_VISAMP (B*2*M)
#define OFF_CPHASE (OFF_VISAMP + B*M)
#define OFF_LOGCAMP (OFF_CPHASE + B*NCP)

// ---- device scratch (no allocation allowed) ----
__device__ __nv_bfloat16 g_cosHi[M*KFOLD];    // [m][c], c fastest
__device__ __nv_bfloat16 g_cosLo[M*KFOLD];
__device__ __nv_bfloat16 g_sinHi[M*KFOLD];
__device__ __nv_bfloat16 g_sinLo[M*KFOLD];
__device__ float2        g_Eu[M*NPIX];        // [m][x]  (er, ei)
__device__ __nv_bfloat16 g_PHi[B*NPIX*KFOLD]; // [b][x][c], c fastest
__device__ __nv_bfloat16 g_PLo[B*NPIX*KFOLD];
__device__ __nv_bfloat16 g_QHi[B*NPIX*KFOLD];
__device__ __nv_bfloat16 g_QLo[B*NPIX*KFOLD];
__device__ float g_visR[B*M];
__device__ float g_visI[B*M];

// ---------------------------------------------------------------------------
// m16n8k16 bf16 mma (baseline PTX, no arch-suffix gating -> ok on sm_103)
// ---------------------------------------------------------------------------
__device__ __forceinline__ void mma16816(float* d, const uint32_t* a, const uint32_t* b) {
    asm volatile(
        "mma.sync.aligned.m16n8k16.row.col.f32.bf16.bf16.f32 "
        "{%0,%1,%2,%3}, {%4,%5,%6,%7}, {%8,%9}, {%0,%1,%2,%3};"
        : "+f"(d[0]), "+f"(d[1]), "+f"(d[2]), "+f"(d[3])
        : "r"(a[0]), "r"(a[1]), "r"(a[2]), "r"(a[3]), "r"(b[0]), "r"(b[1]));
}
__device__ __forceinline__ uint32_t smem_u32(const void* p) {
    uint32_t a;
    asm("{ .reg .u64 t; cvta.to.shared.u64 t, %1; cvt.u32.u64 %0, t; }" : "=r"(a) : "l"(p));
    return a;
}
__device__ __forceinline__ void cp_async16(uint32_t dst, const void* src) {
    asm volatile("cp.async.cg.shared.global [%0], [%1], 16;" :: "r"(dst), "l"(src));
}
#define CP_COMMIT()  asm volatile("cp.async.commit_group;" ::: "memory")
#define CP_WAIT1()   asm volatile("cp.async.wait_group 1;" ::: "memory")
#define CP_WAIT0()   asm volatile("cp.async.wait_group 0;" ::: "memory")

// ---------------- SMEM layout ----------------
// APAD = 40 bf16 (80 bytes) row stride: conflict-free fragment LDS
#define APAD_B   80
#define A_ARR_B  (64 * APAD_B)      // 5120
#define B_ARR_B  (256 * APAD_B)     // 20480
#define STAGE_B  (4 * A_ARR_B + 4 * B_ARR_B)   // 102400 per buffer
#define SM_A(buf, arr)  ((buf) * STAGE_B + (arr) * A_ARR_B)
#define SM_B(buf, arr)  ((buf) * STAGE_B + 4 * A_ARR_B + (arr) * B_ARR_B)
#define SM_IMG      (2 * STAGE_B)                        // 204800, 256 floats
#define SM_REDR     (SM_IMG + 1024)
#define SM_REDI     (SM_REDR + 2048)
#define SM_TOTAL    (SM_REDI + 2048)                     // 209920

// ---------------------------------------------------------------------------
// Kernel 1: trig tables.  Eu uses conjugate symmetry: Eu(256-x) = conj(Eu(x)).
// ---------------------------------------------------------------------------
__global__ void trig_kernel(const float* __restrict__ ktraj) {
    int idx = blockIdx.x * blockDim.x + threadIdx.x;
    if (idx < M * KFOLD) {            // [m][c], c fastest
        int c = idx & (KFOLD - 1);
        int m = idx >> 7;
        float s, co;
        sincosf(ktraj[m] * (float)(c + 1), &s, &co);
        __nv_bfloat16 ch = __float2bfloat16(co);
        __nv_bfloat16 sh = __float2bfloat16(s);
        g_cosHi[idx] = ch;
        g_cosLo[idx] = __float2bfloat16(co - __bfloat162float(ch));
        g_sinHi[idx] = sh;
        g_sinLo[idx] = __float2bfloat16(s - __bfloat162float(sh));
    }
    if (idx < M * NPIX) {             // [m][x], x fastest
        int x = idx & (NPIX - 1);
        int m = idx >> 8;
        if (x <= 128) {
            float cx = (float)(x - NPIX / 2);
            float s, co;
            sincosf(ktraj[M + m] * cx, &s, &co);
            g_Eu[m * NPIX + x] = make_float2(co, -s);
            if (x > 0 && x < 128)
                g_Eu[m * NPIX + (NPIX - x)] = make_float2(co, s);  // conj
        }
    }
}

// ---------------------------------------------------------------------------
// Kernel 1b: fold image, bf16 split, layout [b][x][c]
// ---------------------------------------------------------------------------
__global__ void fold_kernel(const float* __restrict__ img) {
    int idx = blockIdx.x * blockDim.x + threadIdx.x;
    if (idx >= B * NPIX * KFOLD) return;
    int c = idx & (KFOLD - 1);
    int x = (idx >> 7) & (NPIX - 1);
    int b = idx >> 15;
    int cc = c + 1;
    const float* im = img + (size_t)b * NPIX * NPIX;
    float p, q;
    if (cc < 128) {
        float hi = im[(128 + cc) * NPIX + x];
        float lo = im[(128 - cc) * NPIX + x];
        p = hi + lo; q = hi - lo;
    } else {
        float v = im[x];
        p = v; q = -v;
    }
    __nv_bfloat16 ph = __float2bfloat16(p);
    __nv_bfloat16 qh = __float2bfloat16(q);
    g_PHi[idx] = ph;
    g_PLo[idx] = __float2bfloat16(p - __bfloat162float(ph));
    g_QHi[idx] = qh;
    g_QLo[idx] = __float2bfloat16(q - __bfloat162float(qh));
}

// ---------------------------------------------------------------------------
// Kernel 2: HMMA stage with cp.async double-buffered staging.
// CTA = (64 m, one b), 8 warps; warp w owns x in [32w, 32w+32).
// ---------------------------------------------------------------------------
__global__ __launch_bounds__(256, 1) void dft_mma_kernel(
    const float* __restrict__ img,
    const float* __restrict__ pulsefac,
    float* __restrict__ out)
{
    extern __shared__ char sm[];
    const uint32_t smb = smem_u32(sm);

    const int b    = blockIdx.y;
    const int m0   = blockIdx.x * MTILE;
    const int tid  = threadIdx.x;
    const int warp = tid >> 5;
    const int lane = tid & 31;
    const int r    = lane >> 2;
    const int cp   = lane & 3;
    const int wx   = warp * 32;

    float accR[4][4][4], accI[4][4][4];
    #pragma unroll
    for (int i = 0; i < 4; ++i)
        #pragma unroll
        for (int j = 0; j < 4; ++j)
            #pragma unroll
            for (int k = 0; k < 4; ++k) { accR[i][j][k] = 0.f; accI[i][j][k] = 0.f; }

    ((float*)(sm + SM_IMG))[tid] = img[((size_t)b * NPIX + 128) * NPIX + tid];

    const __nv_bfloat16* gA[4] = {g_cosHi, g_cosLo, g_sinHi, g_sinLo};
    const __nv_bfloat16* gB[4] = {g_PHi, g_PLo, g_QHi, g_QLo};

    // cp.async staging of one K-chunk (32 c) into buffer `buf`
    auto stage = [&](int buf, int chunk) {
        const int c0 = chunk * 32;
        #pragma unroll
        for (int t = tid; t < 1024; t += 256) {       // A: 4 arr x 64 rows x 4 x 16B
            int arr = t >> 8, rem = t & 255, row = rem >> 2, seg = rem & 3;
            cp_async16(smb + SM_A(buf, arr) + row * APAD_B + seg * 16,
                       gA[arr] + ((size_t)(m0 + row)) * KFOLD + c0 + seg * 8);
        }
        #pragma unroll
        for (int t = tid; t < 4096; t += 256) {       // B: 4 arr x 256 rows x 4 x 16B
            int arr = t >> 10, rem = t & 1023, row = rem >> 2, seg = rem & 3;
            cp_async16(smb + SM_B(buf, arr) + row * APAD_B + seg * 16,
                       gB[arr] + ((size_t)(b * NPIX + row)) * KFOLD + c0 + seg * 8);
        }
    };

    stage(0, 0);
    CP_COMMIT();

    for (int chunk = 0; chunk < 4; ++chunk) {
        const int buf = chunk & 1;
        if (chunk < 3) { stage(buf ^ 1, chunk + 1); CP_COMMIT(); }
        if (chunk < 3) CP_WAIT1(); else CP_WAIT0();
        __syncthreads();

        #pragma unroll
        for (int ks = 0; ks < 2; ++ks) {
            const int kb = ks * 32 + cp * 4;
            uint32_t aH[4][4], aL[4][4], bH[4][2], bL[4][2];

            // ---- real part: cos x P ----
            #pragma unroll
            for (int tm = 0; tm < 4; ++tm) {
                const char* pH = sm + SM_A(buf, 0) + (tm * 16 + r) * APAD_B + kb;
                const char* pL = sm + SM_A(buf, 1) + (tm * 16 + r) * APAD_B + kb;
                aH[tm][0] = *(const uint32_t*)(pH);
                aH[tm][1] = *(const uint32_t*)(pH + 8 * APAD_B);
                aH[tm][2] = *(const uint32_t*)(pH + 16);
                aH[tm][3] = *(const uint32_t*)(pH + 8 * APAD_B + 16);
                aL[tm][0] = *(const uint32_t*)(pL);
                aL[tm][1] = *(const uint32_t*)(pL + 8 * APAD_B);
                aL[tm][2] = *(const uint32_t*)(pL + 16);
                aL[tm][3] = *(const uint32_t*)(pL + 8 * APAD_B + 16);
            }
            #pragma unroll
            for (int tx = 0; tx < 4; ++tx) {
                const char* pH = sm + SM_B(buf, 0) + (wx + tx * 8 + r) * APAD_B + kb;
                const char* pL = sm + SM_B(buf, 1) + (wx + tx * 8 + r) * APAD_B + kb;
                bH[tx][0] = *(const uint32_t*)(pH);
                bH[tx][1] = *(const uint32_t*)(pH + 16);
                bL[tx][0] = *(const uint32_t*)(pL);
                bL[tx][1] = *(const uint32_t*)(pL + 16);
            }
            #pragma unroll
            for (int tm = 0; tm < 4; ++tm)
                #pragma unroll
                for (int tx = 0; tx < 4; ++tx) {
                    mma16816(accR[tm][tx], aH[tm], bH[tx]);
                    mma16816(accR[tm][tx], aH[tm], bL[tx]);
                    mma16816(accR[tm][tx], aL[tm], bH[tx]);
                }

            // ---- imag part: sin x Q ----
            #pragma unroll
            for (int tm = 0; tm < 4; ++tm) {
                const char* pH = sm + SM_A(buf, 2) + (tm * 16 + r) * APAD_B + kb;
                const char* pL = sm + SM_A(buf, 3) + (tm * 16 + r) * APAD_B + kb;
                aH[tm][0] = *(const uint32_t*)(pH);
                aH[tm][1] = *(const uint32_t*)(pH + 8 * APAD_B);
                aH[tm][2] = *(const uint32_t*)(pH + 16);
                aH[tm][3] = *(const uint32_t*)(pH + 8 * APAD_B + 16);
                aL[tm][0] = *(const uint32_t*)(pL);
                aL[tm][1] = *(const uint32_t*)(pL + 8 * APAD_B);
                aL[tm][2] = *(const uint32_t*)(pL + 16);
                aL[tm][3] = *(const uint32_t*)(pL + 8 * APAD_B + 16);
            }
            #pragma unroll
            for (int tx = 0; tx < 4; ++tx) {
                const char* pH = sm + SM_B(buf, 2) + (wx + tx * 8 + r) * APAD_B + kb;
                const char* pL = sm + SM_B(buf, 3) + (wx + tx * 8 + r) * APAD_B + kb;
                bH[tx][0] = *(const uint32_t*)(pH);
                bH[tx][1] = *(const uint32_t*)(pH + 16);
                bL[tx][0] = *(const uint32_t*)(pL);
                bL[tx][1] = *(const uint32_t*)(pL + 16);
            }
            #pragma unroll
            for (int tm = 0; tm < 4; ++tm)
                #pragma unroll
                for (int tx = 0; tx < 4; ++tx) {
                    mma16816(accI[tm][tx], aH[tm], bH[tx]);
                    mma16816(accI[tm][tx], aH[tm], bL[tx]);
                    mma16816(accI[tm][tx], aL[tm], bH[tx]);
                }
        }
        __syncthreads();   // compute done before next iteration's prefetch overwrites
    }

    // ---- epilogue: T = accR - i*accI (+ center row), contract x with Eu ----
    const float* s_img = (const float*)(sm + SM_IMG);
    float pr[4][2], pim[4][2];
    #pragma unroll
    for (int tm = 0; tm < 4; ++tm)
        #pragma unroll
        for (int h = 0; h < 2; ++h) { pr[tm][h] = 0.f; pim[tm][h] = 0.f; }

    #pragma unroll
    for (int tm = 0; tm < 4; ++tm)
        #pragma unroll
        for (int h = 0; h < 2; ++h) {
            int m = tm * 16 + r + h * 8;
            #pragma unroll
            for (int tx = 0; tx < 4; ++tx) {
                int x = wx + tx * 8 + cp * 2;
                float4 e = *(const float4*)(g_Eu + (size_t)(m0 + m) * NPIX + x);
                float tR0 = accR[tm][tx][h * 2 + 0] + s_img[x];
                float tR1 = accR[tm][tx][h * 2 + 1] + s_img[x + 1];
                float tI0 = accI[tm][tx][h * 2 + 0];
                float tI1 = accI[tm][tx][h * 2 + 1];
                pr[tm][h]  = fmaf(tR0, e.x, fmaf(tI0, e.y, fmaf(tR1, e.z, fmaf(tI1, e.w, pr[tm][h]))));
                pim[tm][h] = fmaf(tR0, e.y, fmaf(-tI0, e.x, fmaf(tR1, e.w, fmaf(-tI1, e.z, pim[tm][h]))));
            }
        }
    #pragma unroll
    for (int tm = 0; tm < 4; ++tm)
        #pragma unroll
        for (int h = 0; h < 2; ++h) {
            pr[tm][h]  += __shfl_xor_sync(0xffffffffu, pr[tm][h], 1);
            pr[tm][h]  += __shfl_xor_sync(0xffffffffu, pr[tm][h], 2);
            pim[tm][h] += __shfl_xor_sync(0xffffffffu, pim[tm][h], 1);
            pim[tm][h] += __shfl_xor_sync(0xffffffffu, pim[tm][h], 2);
        }
    float* sredR = (float*)(sm + SM_REDR);
    float* sredI = (float*)(sm + SM_REDI);
    if (cp == 0) {
        #pragma unroll
        for (int tm = 0; tm < 4; ++tm)
            #pragma unroll
            for (int h = 0; h < 2; ++h) {
                int ml = tm * 16 + r + h * 8;
                sredR[warp * 64 + ml] = pr[tm][h];
                sredI[warp * 64 + ml] = pim[tm][h];
            }
    }
    __syncthreads();

    if (tid < 64) {
        float PR = 0.f, PIM = 0.f;
        #pragma unroll
        for (int w = 0; w < 8; ++w) { PR += sredR[w * 64 + tid]; PIM += sredI[w * 64 + tid]; }
        int m = m0 + tid;
        float p0 = pulsefac[m];
        float p1 = pulsefac[M + m];
        float re = PR * p0 - PIM * p1;
        float im = PR * p1 + PIM * p0;
        out[OFF_VIS + (b * 2) * M + m]     = re;
        out[OFF_VIS + (b * 2 + 1) * M + m] = im;
        out[OFF_VISAMP + b * M + m] = sqrtf(re * re + im * im + FEPS);
        g_visR[b * M + m] = re;
        g_visI[b * M + m] = im;
    }
}

// ---------------------------------------------------------------------------
// Kernel 3: closure phases
// ---------------------------------------------------------------------------
__global__ void cphase_kernel(const float* __restrict__ sign,
                              const int* __restrict__ ind,
                              float* __restrict__ out) {
    int idx = blockIdx.x * blockDim.x + threadIdx.x;
    if (idx >= B * NCP) return;
    int b = idx / NCP;
    int n = idx - b * NCP;
    float s = 0.f;
    #pragma unroll
    for (int k = 0; k < 3; ++k) {
        int id   = ind[k * NCP + n];
        float sg = sign[k * NCP + n];
        s += sg * atan2f(g_visI[b * M + id], g_visR[b * M + id]);
    }
    out[OFF_CPHASE + idx] = s * 57.29577951308232f;
}

// ---------------------------------------------------------------------------
// Kernel 4: log closure amplitudes (fast __logf: abs err ~1e-6, fine)
// ---------------------------------------------------------------------------
__global__ void logcamp_kernel(const int* __restrict__ ind,
                               float* __restrict__ out) {
    int idx = blockIdx.x * blockDim.x + threadIdx.x;
    if (idx >= B * NCA) return;
    int b = idx / NCA;
    int n = idx - b * NCA;
    float la[4];
    #pragma unroll
    for (int k = 0; k < 4; ++k) {
        int id   = ind[k * NCA + n];
        float re = g_visR[b * M + id];
        float im = g_visI[b * M + id];
        la[k] = 0.5f * __logf(re * re + im * im + FEPS);
    }
    out[OFF_LOGCAMP + idx] = la[0] + la[1] - la[2] - la[3];
}

extern "C" void kernel_launch(void* const* d_in, const int* in_sizes, int n_in,
                              void* d_out, int out_size) {
    const float* images      = (const float*)d_in[0];
    const float* ktraj       = (const float*)d_in[1];
    const float* pulsefac    = (const float*)d_in[2];
    const float* cphase_sign = (const float*)d_in[3];
    const int*   cphase_ind  = (const int*)d_in[4];
    const int*   camp_ind    = (const int*)d_in[5];
    float* out = (float*)d_out;

    cudaFuncSetAttribute(dft_mma_kernel, cudaFuncAttributeMaxDynamicSharedMemorySize, SM_TOTAL);

    trig_kernel<<<(M * NPIX) / 256, 256>>>(ktraj);
    fold_kernel<<<(B * NPIX * KFOLD) / 256, 256>>>(images);

    dim3 grid(M / MTILE, B);
    dft_mma_kernel<<<grid, 256, SM_TOTAL>>>(images, pulsefac, out);

    cphase_kernel<<<(B * NCP + 255) / 256, 256>>>(cphase_sign, cphase_ind, out);
    logcamp_kernel<<<(B * NCA + 255) / 256, 256>>>(camp_ind, out);
}

// round 12
// speedup vs baseline: 2.5518x; 1.0279x over previous
#include <cuda_runtime.h>
#include <cuda_bf16.h>
#include <cstdint>
#include <math.h>

#define B 8
#define NPIX 256
#define M 8192
#define NCP 24576
#define NCA 24576
#define FEPS 1e-16f
#define KFOLD 128
#define MTILE 64

#define OFF_VIS 0
#define OFF_VISAMP (B*2*M)
#define OFF_CPHASE (OFF_VISAMP + B*M)
#define OFF_LOGCAMP (OFF_CPHASE + B*NCP)

// ---- device scratch (no allocation allowed) ----
__device__ __nv_bfloat16 g_cosHi[M*KFOLD];    // [m][c], c fastest
__device__ __nv_bfloat16 g_cosLo[M*KFOLD];
__device__ __nv_bfloat16 g_sinHi[M*KFOLD];
__device__ __nv_bfloat16 g_sinLo[M*KFOLD];
__device__ float2        g_Eu[M*NPIX];        // [m][x]  (er, ei)
__device__ __nv_bfloat16 g_PHi[B*NPIX*KFOLD]; // [b][x][c], c fastest
__device__ __nv_bfloat16 g_PLo[B*NPIX*KFOLD];
__device__ __nv_bfloat16 g_QHi[B*NPIX*KFOLD];
__device__ __nv_bfloat16 g_QLo[B*NPIX*KFOLD];
__device__ float g_visR[B*M];
__device__ float g_visI[B*M];

// ---------------------------------------------------------------------------
// m16n8k16 bf16 mma (baseline PTX, no arch-suffix gating -> ok on sm_103)
// ---------------------------------------------------------------------------
__device__ __forceinline__ void mma16816(float* d, const uint32_t* a, const uint32_t* b) {
    asm volatile(
        "mma.sync.aligned.m16n8k16.row.col.f32.bf16.bf16.f32 "
        "{%0,%1,%2,%3}, {%4,%5,%6,%7}, {%8,%9}, {%0,%1,%2,%3};"
        : "+f"(d[0]), "+f"(d[1]), "+f"(d[2]), "+f"(d[3])
        : "r"(a[0]), "r"(a[1]), "r"(a[2]), "r"(a[3]), "r"(b[0]), "r"(b[1]));
}
__device__ __forceinline__ uint32_t smem_u32(const void* p) {
    uint32_t a;
    asm("{ .reg .u64 t; cvta.to.shared.u64 t, %1; cvt.u32.u64 %0, t; }" : "=r"(a) : "l"(p));
    return a;
}
__device__ __forceinline__ void cp_async16(uint32_t dst, const void* src) {
    asm volatile("cp.async.cg.shared.global [%0], [%1], 16;" :: "r"(dst), "l"(src));
}
#define CP_COMMIT()  asm volatile("cp.async.commit_group;" ::: "memory")
#define CP_WAIT1()   asm volatile("cp.async.wait_group 1;" ::: "memory")
#define CP_WAIT0()   asm volatile("cp.async.wait_group 0;" ::: "memory")

// ---------------- SMEM layout (dft kernel) ----------------
#define APAD_B   80
#define A_ARR_B  (64 * APAD_B)      // 5120
#define B_ARR_B  (256 * APAD_B)     // 20480
#define STAGE_B  (4 * A_ARR_B + 4 * B_ARR_B)   // 102400 per buffer
#define SM_A(buf, arr)  ((buf) * STAGE_B + (arr) * A_ARR_B)
#define SM_B(buf, arr)  ((buf) * STAGE_B + 4 * A_ARR_B + (arr) * B_ARR_B)
#define SM_IMG      (2 * STAGE_B)
#define SM_REDR     (SM_IMG + 1024)
#define SM_REDI     (SM_REDR + 2048)
#define SM_TOTAL    (SM_REDI + 2048)                     // 209920

// ---------------------------------------------------------------------------
// Kernel 1: trig tables via anchor decomposition + exact FMA residual
// correction.  For each entry the target angle is th = fl(k * c) — the SAME
// fp32 product the reference rounds — and we reconstruct sin/cos(th) to ulp
// accuracy from 65 sincosf anchors per m:
//   k*c = k*8j + k*l  (each anchor a = fl(k*base), residual r = fma(k,base,-a))
//   th  = a8 + a1 + d,   d = r8 + r1 - rth,  rth = fma(k,cf,-th)
//   sin(th) ~= S + d*C,  cos(th) ~= C - d*S   (|d| <= ~7e-5, 2nd order ~2e-9)
// ---------------------------------------------------------------------------
__global__ void trig_kernel(const float* __restrict__ ktraj) {
    __shared__ float sc[65], ss[65], sr[65];
    const int m   = blockIdx.x;
    const int lid = threadIdx.x;
    const float kv = ktraj[m];
    const float ku = ktraj[M + m];

    if (lid < 65) {
        float base, k;
        if (lid < 17)      { base = (float)(8 * lid);             k = kv; }
        else if (lid < 25) { base = (float)(lid - 17);            k = kv; }
        else if (lid < 57) { base = (float)(8 * (lid - 25 - 16)); k = ku; }
        else               { base = (float)(lid - 57);            k = ku; }
        float a = k * base;
        float r = fmaf(k, base, -a);   // exact: k*base = a + r
        float s, c;
        sincosf(a, &s, &c);
        sc[lid] = c; ss[lid] = s; sr[lid] = r;
    }
    __syncthreads();

    if (lid < 128) {                   // A tables: c' = lid+1 in [1,128]
        int cc = lid + 1;
        int j = cc >> 3, l = cc & 7;
        float cf  = (float)cc;
        float th  = kv * cf;
        float rth = fmaf(kv, cf, -th);
        float d   = sr[j] + sr[17 + l] - rth;
        float C = sc[j] * sc[17 + l] - ss[j] * ss[17 + l];
        float S = ss[j] * sc[17 + l] + sc[j] * ss[17 + l];
        float Cc = fmaf(-d, S, C);
        float Sc = fmaf( d, C, S);
        __nv_bfloat16 ch = __float2bfloat16(Cc);
        __nv_bfloat16 sh = __float2bfloat16(Sc);
        int o = m * KFOLD + lid;
        g_cosHi[o] = ch;
        g_cosLo[o] = __float2bfloat16(Cc - __bfloat162float(ch));
        g_sinHi[o] = sh;
        g_sinLo[o] = __float2bfloat16(Sc - __bfloat162float(sh));
    }
    {                                  // Eu: x = lid in [0,256)
        int x = lid;
        int j = x >> 3, l = x & 7;
        float cxf = (float)(x - 128);
        float th  = ku * cxf;
        float rth = fmaf(ku, cxf, -th);
        float d   = sr[25 + j] + sr[57 + l] - rth;
        float C = sc[25 + j] * sc[57 + l] - ss[25 + j] * ss[57 + l];
        float S = ss[25 + j] * sc[57 + l] + sc[25 + j] * ss[57 + l];
        float Cc = fmaf(-d, S, C);
        float Sc = fmaf( d, C, S);
        g_Eu[m * NPIX + x] = make_float2(Cc, -Sc);
    }
}

// ---------------------------------------------------------------------------
// Kernel 1b: fold image, bf16 split, layout [b][x][c]
// ---------------------------------------------------------------------------
__global__ void fold_kernel(const float* __restrict__ img) {
    int idx = blockIdx.x * blockDim.x + threadIdx.x;
    if (idx >= B * NPIX * KFOLD) return;
    int c = idx & (KFOLD - 1);
    int x = (idx >> 7) & (NPIX - 1);
    int b = idx >> 15;
    int cc = c + 1;
    const float* im = img + (size_t)b * NPIX * NPIX;
    float p, q;
    if (cc < 128) {
        float hi = im[(128 + cc) * NPIX + x];
        float lo = im[(128 - cc) * NPIX + x];
        p = hi + lo; q = hi - lo;
    } else {
        float v = im[x];
        p = v; q = -v;
    }
    __nv_bfloat16 ph = __float2bfloat16(p);
    __nv_bfloat16 qh = __float2bfloat16(q);
    g_PHi[idx] = ph;
    g_PLo[idx] = __float2bfloat16(p - __bfloat162float(ph));
    g_QHi[idx] = qh;
    g_QLo[idx] = __float2bfloat16(q - __bfloat162float(qh));
}

// ---------------------------------------------------------------------------
// Kernel 2: HMMA stage (identical to the validated Round-8 mainloop).
// bf16 3-product split: acc = aHi*bHi + aHi*bLo + aLo*bHi.
// CTA = (64 m, one b), 8 warps; warp w owns x in [32w, 32w+32).
// ---------------------------------------------------------------------------
__global__ __launch_bounds__(256, 1) void dft_mma_kernel(
    const float* __restrict__ img,
    const float* __restrict__ pulsefac,
    float* __restrict__ out)
{
    extern __shared__ char sm[];
    const uint32_t smb = smem_u32(sm);

    const int b    = blockIdx.y;
    const int m0   = blockIdx.x * MTILE;
    const int tid  = threadIdx.x;
    const int warp = tid >> 5;
    const int lane = tid & 31;
    const int r    = lane >> 2;
    const int cp   = lane & 3;
    const int wx   = warp * 32;

    float accR[4][4][4], accI[4][4][4];
    #pragma unroll
    for (int i = 0; i < 4; ++i)
        #pragma unroll
        for (int j = 0; j < 4; ++j)
            #pragma unroll
            for (int k = 0; k < 4; ++k) { accR[i][j][k] = 0.f; accI[i][j][k] = 0.f; }

    ((float*)(sm + SM_IMG))[tid] = img[((size_t)b * NPIX + 128) * NPIX + tid];

    const __nv_bfloat16* gA[4] = {g_cosHi, g_cosLo, g_sinHi, g_sinLo};
    const __nv_bfloat16* gB[4] = {g_PHi, g_PLo, g_QHi, g_QLo};

    auto stage = [&](int buf, int chunk) {
        const int c0 = chunk * 32;
        #pragma unroll
        for (int t = tid; t < 1024; t += 256) {
            int arr = t >> 8, rem = t & 255, row = rem >> 2, seg = rem & 3;
            cp_async16(smb + SM_A(buf, arr) + row * APAD_B + seg * 16,
                       gA[arr] + ((size_t)(m0 + row)) * KFOLD + c0 + seg * 8);
        }
        #pragma unroll
        for (int t = tid; t < 4096; t += 256) {
            int arr = t >> 10, rem = t & 1023, row = rem >> 2, seg = rem & 3;
            cp_async16(smb + SM_B(buf, arr) + row * APAD_B + seg * 16,
                       gB[arr] + ((size_t)(b * NPIX + row)) * KFOLD + c0 + seg * 8);
        }
    };

    stage(0, 0);
    CP_COMMIT();

    for (int chunk = 0; chunk < 4; ++chunk) {
        const int buf = chunk & 1;
        if (chunk < 3) { stage(buf ^ 1, chunk + 1); CP_COMMIT(); }
        if (chunk < 3) CP_WAIT1(); else CP_WAIT0();
        __syncthreads();

        #pragma unroll
        for (int ks = 0; ks < 2; ++ks) {
            const int kb = ks * 32 + cp * 4;
            uint32_t aH[4][4], aL[4][4], bH[4][2], bL[4][2];

            // ---- real part: cos x P ----
            #pragma unroll
            for (int tm = 0; tm < 4; ++tm) {
                const char* pH = sm + SM_A(buf, 0) + (tm * 16 + r) * APAD_B + kb;
                const char* pL = sm + SM_A(buf, 1) + (tm * 16 + r) * APAD_B + kb;
                aH[tm][0] = *(const uint32_t*)(pH);
                aH[tm][1] = *(const uint32_t*)(pH + 8 * APAD_B);
                aH[tm][2] = *(const uint32_t*)(pH + 16);
                aH[tm][3] = *(const uint32_t*)(pH + 8 * APAD_B + 16);
                aL[tm][0] = *(const uint32_t*)(pL);
                aL[tm][1] = *(const uint32_t*)(pL + 8 * APAD_B);
                aL[tm][2] = *(const uint32_t*)(pL + 16);
                aL[tm][3] = *(const uint32_t*)(pL + 8 * APAD_B + 16);
            }
            #pragma unroll
            for (int tx = 0; tx < 4; ++tx) {
                const char* pH = sm + SM_B(buf, 0) + (wx + tx * 8 + r) * APAD_B + kb;
                const char* pL = sm + SM_B(buf, 1) + (wx + tx * 8 + r) * APAD_B + kb;
                bH[tx][0] = *(const uint32_t*)(pH);
                bH[tx][1] = *(const uint32_t*)(pH + 16);
                bL[tx][0] = *(const uint32_t*)(pL);
                bL[tx][1] = *(const uint32_t*)(pL + 16);
            }
            #pragma unroll
            for (int tm = 0; tm < 4; ++tm)
                #pragma unroll
                for (int tx = 0; tx < 4; ++tx) {
                    mma16816(accR[tm][tx], aH[tm], bH[tx]);
                    mma16816(accR[tm][tx], aH[tm], bL[tx]);
                    mma16816(accR[tm][tx], aL[tm], bH[tx]);
                }

            // ---- imag part: sin x Q ----
            #pragma unroll
            for (int tm = 0; tm < 4; ++tm) {
                const char* pH = sm + SM_A(buf, 2) + (tm * 16 + r) * APAD_B + kb;
                const char* pL = sm + SM_A(buf, 3) + (tm * 16 + r) * APAD_B + kb;
                aH[tm][0] = *(const uint32_t*)(pH);
                aH[tm][1] = *(const uint32_t*)(pH + 8 * APAD_B);
                aH[tm][2] = *(const uint32_t*)(pH + 16);
                aH[tm][3] = *(const uint32_t*)(pH + 8 * APAD_B + 16);
                aL[tm][0] = *(const uint32_t*)(pL);
                aL[tm][1] = *(const uint32_t*)(pL + 8 * APAD_B);
                aL[tm][2] = *(const uint32_t*)(pL + 16);
                aL[tm][3] = *(const uint32_t*)(pL + 8 * APAD_B + 16);
            }
            #pragma unroll
            for (int tx = 0; tx < 4; ++tx) {
                const char* pH = sm + SM_B(buf, 2) + (wx + tx * 8 + r) * APAD_B + kb;
                const char* pL = sm + SM_B(buf, 3) + (wx + tx * 8 + r) * APAD_B + kb;
                bH[tx][0] = *(const uint32_t*)(pH);
                bH[tx][1] = *(const uint32_t*)(pH + 16);
                bL[tx][0] = *(const uint32_t*)(pL);
                bL[tx][1] = *(const uint32_t*)(pL + 16);
            }
            #pragma unroll
            for (int tm = 0; tm < 4; ++tm)
                #pragma unroll
                for (int tx = 0; tx < 4; ++tx) {
                    mma16816(accI[tm][tx], aH[tm], bH[tx]);
                    mma16816(accI[tm][tx], aH[tm], bL[tx]);
                    mma16816(accI[tm][tx], aL[tm], bH[tx]);
                }
        }
        __syncthreads();
    }

    // ---- epilogue: T = accR - i*accI (+ center row), contract x with Eu ----
    const float* s_img = (const float*)(sm + SM_IMG);
    float pr[4][2], pim[4][2];
    #pragma unroll
    for (int tm = 0; tm < 4; ++tm)
        #pragma unroll
        for (int h = 0; h < 2; ++h) { pr[tm][h] = 0.f; pim[tm][h] = 0.f; }

    #pragma unroll
    for (int tm = 0; tm < 4; ++tm)
        #pragma unroll
        for (int h = 0; h < 2; ++h) {
            int m = tm * 16 + r + h * 8;
            #pragma unroll
            for (int tx = 0; tx < 4; ++tx) {
                int x = wx + tx * 8 + cp * 2;
                float4 e = *(const float4*)(g_Eu + (size_t)(m0 + m) * NPIX + x);
                float tR0 = accR[tm][tx][h * 2 + 0] + s_img[x];
                float tR1 = accR[tm][tx][h * 2 + 1] + s_img[x + 1];
                float tI0 = accI[tm][tx][h * 2 + 0];
                float tI1 = accI[tm][tx][h * 2 + 1];
                pr[tm][h]  = fmaf(tR0, e.x, fmaf(tI0, e.y, fmaf(tR1, e.z, fmaf(tI1, e.w, pr[tm][h]))));
                pim[tm][h] = fmaf(tR0, e.y, fmaf(-tI0, e.x, fmaf(tR1, e.w, fmaf(-tI1, e.z, pim[tm][h]))));
            }
        }
    #pragma unroll
    for (int tm = 0; tm < 4; ++tm)
        #pragma unroll
        for (int h = 0; h < 2; ++h) {
            pr[tm][h]  += __shfl_xor_sync(0xffffffffu, pr[tm][h], 1);
            pr[tm][h]  += __shfl_xor_sync(0xffffffffu, pr[tm][h], 2);
            pim[tm][h] += __shfl_xor_sync(0xffffffffu, pim[tm][h], 1);
            pim[tm][h] += __shfl_xor_sync(0xffffffffu, pim[tm][h], 2);
        }
    float* sredR = (float*)(sm + SM_REDR);
    float* sredI = (float*)(sm + SM_REDI);
    if (cp == 0) {
        #pragma unroll
        for (int tm = 0; tm < 4; ++tm)
            #pragma unroll
            for (int h = 0; h < 2; ++h) {
                int ml = tm * 16 + r + h * 8;
                sredR[warp * 64 + ml] = pr[tm][h];
                sredI[warp * 64 + ml] = pim[tm][h];
            }
    }
    __syncthreads();

    if (tid < 64) {
        float PR = 0.f, PIM = 0.f;
        #pragma unroll
        for (int w = 0; w < 8; ++w) { PR += sredR[w * 64 + tid]; PIM += sredI[w * 64 + tid]; }
        int m = m0 + tid;
        float p0 = pulsefac[m];
        float p1 = pulsefac[M + m];
        float re = PR * p0 - PIM * p1;
        float im = PR * p1 + PIM * p0;
        out[OFF_VIS + (b * 2) * M + m]     = re;
        out[OFF_VIS + (b * 2 + 1) * M + m] = im;
        out[OFF_VISAMP + b * M + m] = sqrtf(re * re + im * im + FEPS);
        g_visR[b * M + m] = re;
        g_visI[b * M + m] = im;
    }
}

// ---------------------------------------------------------------------------
// Kernel 3: merged closures (cphase + logcamp in one launch)
// ---------------------------------------------------------------------------
__global__ void closure_kernel(const float* __restrict__ sign,
                               const int* __restrict__ cpind,
                               const int* __restrict__ caind,
                               float* __restrict__ out) {
    int idx = blockIdx.x * blockDim.x + threadIdx.x;
    if (idx < B * NCP) {
        int b = idx / NCP;
        int n = idx - b * NCP;
        float s = 0.f;
        #pragma unroll
        for (int k = 0; k < 3; ++k) {
            int id   = cpind[k * NCP + n];
            float sg = sign[k * NCP + n];
            s += sg * atan2f(g_visI[b * M + id], g_visR[b * M + id]);
        }
        out[OFF_CPHASE + idx] = s * 57.29577951308232f;
    } else if (idx < B * (NCP + NCA)) {
        int j = idx - B * NCP;
        int b = j / NCA;
        int n = j - b * NCA;
        float la[4];
        #pragma unroll
        for (int k = 0; k < 4; ++k) {
            int id   = caind[k * NCA + n];
            float re = g_visR[b * M + id];
            float im = g_visI[b * M + id];
            la[k] = 0.5f * __logf(re * re + im * im + FEPS);
        }
        out[OFF_LOGCAMP + j] = la[0] + la[1] - la[2] - la[3];
    }
}

extern "C" void kernel_launch(void* const* d_in, const int* in_sizes, int n_in,
                              void* d_out, int out_size) {
    const float* images      = (const float*)d_in[0];
    const float* ktraj       = (const float*)d_in[1];
    const float* pulsefac    = (const float*)d_in[2];
    const float* cphase_sign = (const float*)d_in[3];
    const int*   cphase_ind  = (const int*)d_in[4];
    const int*   camp_ind    = (const int*)d_in[5];
    float* out = (float*)d_out;

    cudaFuncSetAttribute(dft_mma_kernel, cudaFuncAttributeMaxDynamicSharedMemorySize, SM_TOTAL);

    trig_kernel<<<M, 256>>>(ktraj);
    fold_kernel<<<(B * NPIX * KFOLD) / 256, 256>>>(images);

    dim3 grid(M / MTILE, B);
    dft_mma_kernel<<<grid, 256, SM_TOTAL>>>(images, pulsefac, out);

    closure_kernel<<<(B * (NCP + NCA) + 255) / 256, 256>>>(cphase_sign, cphase_ind, camp_ind, out);
}

// round 13
// speedup vs baseline: 2.5606x; 1.0035x over previous
#include <cuda_runtime.h>
#include <cuda_bf16.h>
#include <cstdint>
#include <math.h>

#define B 8
#define NPIX 256
#define M 8192
#define NCP 24576
#define NCA 24576
#define FEPS 1e-16f
#define KFOLD 128
#define MTILE 64

#define OFF_VIS 0
#define OFF_VISAMP (B*2*M)
#define OFF_CPHASE (OFF_VISAMP + B*M)
#define OFF_LOGCAMP (OFF_CPHASE + B*NCP)

// ---- device scratch (no allocation allowed) ----
__device__ __nv_bfloat16 g_cosHi[M*KFOLD];    // [m][c], c fastest
__device__ __nv_bfloat16 g_cosLo[M*KFOLD];
__device__ __nv_bfloat16 g_sinHi[M*KFOLD];
__device__ __nv_bfloat16 g_sinLo[M*KFOLD];
__device__ float2        g_Eu[M*NPIX];        // [m][x]  (er, ei)
__device__ __nv_bfloat16 g_PHi[B*NPIX*KFOLD]; // [b][x][c], c fastest
__device__ __nv_bfloat16 g_PLo[B*NPIX*KFOLD];
__device__ __nv_bfloat16 g_QHi[B*NPIX*KFOLD];
__device__ __nv_bfloat16 g_QLo[B*NPIX*KFOLD];
__device__ float g_visR[B*M];
__device__ float g_visI[B*M];

// ---------------------------------------------------------------------------
// m16n8k16 bf16 mma (baseline PTX, no arch-suffix gating -> ok on sm_103)
// ---------------------------------------------------------------------------
__device__ __forceinline__ void mma16816(float* d, const uint32_t* a, const uint32_t* b) {
    asm volatile(
        "mma.sync.aligned.m16n8k16.row.col.f32.bf16.bf16.f32 "
        "{%0,%1,%2,%3}, {%4,%5,%6,%7}, {%8,%9}, {%0,%1,%2,%3};"
        : "+f"(d[0]), "+f"(d[1]), "+f"(d[2]), "+f"(d[3])
        : "r"(a[0]), "r"(a[1]), "r"(a[2]), "r"(a[3]), "r"(b[0]), "r"(b[1]));
}
__device__ __forceinline__ uint32_t smem_u32(const void* p) {
    uint32_t a;
    asm("{ .reg .u64 t; cvta.to.shared.u64 t, %1; cvt.u32.u64 %0, t; }" : "=r"(a) : "l"(p));
    return a;
}
__device__ __forceinline__ void cp_async16(uint32_t dst, const void* src) {
    asm volatile("cp.async.cg.shared.global [%0], [%1], 16;" :: "r"(dst), "l"(src));
}
#define CP_COMMIT()  asm volatile("cp.async.commit_group;" ::: "memory")
#define CP_WAIT1()   asm volatile("cp.async.wait_group 1;" ::: "memory")
#define CP_WAIT0()   asm volatile("cp.async.wait_group 0;" ::: "memory")

// ---------------- SMEM layout (dft kernel) ----------------
#define APAD_B   80
#define A_ARR_B  (64 * APAD_B)      // 5120
#define B_ARR_B  (256 * APAD_B)     // 20480
#define STAGE_B  (4 * A_ARR_B + 4 * B_ARR_B)   // 102400 per buffer
#define SM_A(buf, arr)  ((buf) * STAGE_B + (arr) * A_ARR_B)
#define SM_B(buf, arr)  ((buf) * STAGE_B + 4 * A_ARR_B + (arr) * B_ARR_B)
#define SM_IMG      (2 * STAGE_B)
#define SM_REDR     (SM_IMG + 1024)
#define SM_REDI     (SM_REDR + 2048)
#define SM_TOTAL    (SM_REDI + 2048)                     // 209920

// ---------------------------------------------------------------------------
// Kernel 1: trig tables via anchor decomposition + exact FMA residual
// correction (validated R12).  128 threads/block; each thread writes one A
// entry and two Eu entries (fewer idle threads than the 256-thread version).
// ---------------------------------------------------------------------------
__global__ void trig_kernel(const float* __restrict__ ktraj) {
    __shared__ float sc[65], ss[65], sr[65];
    const int m   = blockIdx.x;
    const int lid = threadIdx.x;          // 0..127
    const float kv = ktraj[m];
    const float ku = ktraj[M + m];

    if (lid < 65) {
        float base, k;
        if (lid < 17)      { base = (float)(8 * lid);             k = kv; }
        else if (lid < 25) { base = (float)(lid - 17);            k = kv; }
        else if (lid < 57) { base = (float)(8 * (lid - 25 - 16)); k = ku; }
        else               { base = (float)(lid - 57);            k = ku; }
        float a = k * base;
        float r = fmaf(k, base, -a);   // exact: k*base = a + r
        float s, c;
        sincosf(a, &s, &c);
        sc[lid] = c; ss[lid] = s; sr[lid] = r;
    }
    __syncthreads();

    {                                  // A tables: c' = lid+1 in [1,128]
        int cc = lid + 1;
        int j = cc >> 3, l = cc & 7;
        float cf  = (float)cc;
        float th  = kv * cf;
        float rth = fmaf(kv, cf, -th);
        float d   = sr[j] + sr[17 + l] - rth;
        float C = sc[j] * sc[17 + l] - ss[j] * ss[17 + l];
        float S = ss[j] * sc[17 + l] + sc[j] * ss[17 + l];
        float Cc = fmaf(-d, S, C);
        float Sc = fmaf( d, C, S);
        __nv_bfloat16 ch = __float2bfloat16(Cc);
        __nv_bfloat16 sh = __float2bfloat16(Sc);
        int o = m * KFOLD + lid;
        g_cosHi[o] = ch;
        g_cosLo[o] = __float2bfloat16(Cc - __bfloat162float(ch));
        g_sinHi[o] = sh;
        g_sinLo[o] = __float2bfloat16(Sc - __bfloat162float(sh));
    }
    #pragma unroll
    for (int xx = 0; xx < 2; ++xx) {   // Eu: x = lid and lid+128
        int x = lid + xx * 128;
        int j = x >> 3, l = x & 7;
        float cxf = (float)(x - 128);
        float th  = ku * cxf;
        float rth = fmaf(ku, cxf, -th);
        float d   = sr[25 + j] + sr[57 + l] - rth;
        float C = sc[25 + j] * sc[57 + l] - ss[25 + j] * ss[57 + l];
        float S = ss[25 + j] * sc[57 + l] + sc[25 + j] * ss[57 + l];
        float Cc = fmaf(-d, S, C);
        float Sc = fmaf( d, C, S);
        g_Eu[m * NPIX + x] = make_float2(Cc, -Sc);
    }
}

// ---------------------------------------------------------------------------
// Kernel 1b: fold image, bf16 split, layout [b][x][c]
// ---------------------------------------------------------------------------
__global__ void fold_kernel(const float* __restrict__ img) {
    int idx = blockIdx.x * blockDim.x + threadIdx.x;
    if (idx >= B * NPIX * KFOLD) return;
    int c = idx & (KFOLD - 1);
    int x = (idx >> 7) & (NPIX - 1);
    int b = idx >> 15;
    int cc = c + 1;
    const float* im = img + (size_t)b * NPIX * NPIX;
    float p, q;
    if (cc < 128) {
        float hi = im[(128 + cc) * NPIX + x];
        float lo = im[(128 - cc) * NPIX + x];
        p = hi + lo; q = hi - lo;
    } else {
        float v = im[x];
        p = v; q = -v;
    }
    __nv_bfloat16 ph = __float2bfloat16(p);
    __nv_bfloat16 qh = __float2bfloat16(q);
    g_PHi[idx] = ph;
    g_PLo[idx] = __float2bfloat16(p - __bfloat162float(ph));
    g_QHi[idx] = qh;
    g_QLo[idx] = __float2bfloat16(q - __bfloat162float(qh));
}

// ---------------------------------------------------------------------------
// Kernel 2: HMMA stage.  Identical math to R8/R12; MMA issue order is now
// PRODUCT-MAJOR (all 16 HH, then 16 HL, then 16 LH) so same-accumulator
// RAW chains have dependency distance 16 instead of 1.
// ---------------------------------------------------------------------------
__global__ __launch_bounds__(256, 1) void dft_mma_kernel(
    const float* __restrict__ img,
    const float* __restrict__ pulsefac,
    float* __restrict__ out)
{
    extern __shared__ char sm[];
    const uint32_t smb = smem_u32(sm);

    const int b    = blockIdx.y;
    const int m0   = blockIdx.x * MTILE;
    const int tid  = threadIdx.x;
    const int warp = tid >> 5;
    const int lane = tid & 31;
    const int r    = lane >> 2;
    const int cp   = lane & 3;
    const int wx   = warp * 32;

    float accR[4][4][4], accI[4][4][4];
    #pragma unroll
    for (int i = 0; i < 4; ++i)
        #pragma unroll
        for (int j = 0; j < 4; ++j)
            #pragma unroll
            for (int k = 0; k < 4; ++k) { accR[i][j][k] = 0.f; accI[i][j][k] = 0.f; }

    ((float*)(sm + SM_IMG))[tid] = img[((size_t)b * NPIX + 128) * NPIX + tid];

    const __nv_bfloat16* gA[4] = {g_cosHi, g_cosLo, g_sinHi, g_sinLo};
    const __nv_bfloat16* gB[4] = {g_PHi, g_PLo, g_QHi, g_QLo};

    auto stage = [&](int buf, int chunk) {
        const int c0 = chunk * 32;
        #pragma unroll
        for (int t = tid; t < 1024; t += 256) {
            int arr = t >> 8, rem = t & 255, row = rem >> 2, seg = rem & 3;
            cp_async16(smb + SM_A(buf, arr) + row * APAD_B + seg * 16,
                       gA[arr] + ((size_t)(m0 + row)) * KFOLD + c0 + seg * 8);
        }
        #pragma unroll
        for (int t = tid; t < 4096; t += 256) {
            int arr = t >> 10, rem = t & 1023, row = rem >> 2, seg = rem & 3;
            cp_async16(smb + SM_B(buf, arr) + row * APAD_B + seg * 16,
                       gB[arr] + ((size_t)(b * NPIX + row)) * KFOLD + c0 + seg * 8);
        }
    };

    stage(0, 0);
    CP_COMMIT();

    for (int chunk = 0; chunk < 4; ++chunk) {
        const int buf = chunk & 1;
        if (chunk < 3) { stage(buf ^ 1, chunk + 1); CP_COMMIT(); }
        if (chunk < 3) CP_WAIT1(); else CP_WAIT0();
        __syncthreads();

        #pragma unroll
        for (int ks = 0; ks < 2; ++ks) {
            const int kb = ks * 32 + cp * 4;
            uint32_t aH[4][4], aL[4][4], bH[4][2], bL[4][2];

            // ======== real part: cos x P ========
            #pragma unroll
            for (int tm = 0; tm < 4; ++tm) {
                const char* pH = sm + SM_A(buf, 0) + (tm * 16 + r) * APAD_B + kb;
                const char* pL = sm + SM_A(buf, 1) + (tm * 16 + r) * APAD_B + kb;
                aH[tm][0] = *(const uint32_t*)(pH);
                aH[tm][1] = *(const uint32_t*)(pH + 8 * APAD_B);
                aH[tm][2] = *(const uint32_t*)(pH + 16);
                aH[tm][3] = *(const uint32_t*)(pH + 8 * APAD_B + 16);
                aL[tm][0] = *(const uint32_t*)(pL);
                aL[tm][1] = *(const uint32_t*)(pL + 8 * APAD_B);
                aL[tm][2] = *(const uint32_t*)(pL + 16);
                aL[tm][3] = *(const uint32_t*)(pL + 8 * APAD_B + 16);
            }
            #pragma unroll
            for (int tx = 0; tx < 4; ++tx) {
                const char* pH = sm + SM_B(buf, 0) + (wx + tx * 8 + r) * APAD_B + kb;
                const char* pL = sm + SM_B(buf, 1) + (wx + tx * 8 + r) * APAD_B + kb;
                bH[tx][0] = *(const uint32_t*)(pH);
                bH[tx][1] = *(const uint32_t*)(pH + 16);
                bL[tx][0] = *(const uint32_t*)(pL);
                bL[tx][1] = *(const uint32_t*)(pL + 16);
            }
            // product-major: HH x16, HL x16, LH x16  (dep distance 16)
            #pragma unroll
            for (int p = 0; p < 3; ++p) {
                #pragma unroll
                for (int tm = 0; tm < 4; ++tm)
                    #pragma unroll
                    for (int tx = 0; tx < 4; ++tx)
                        mma16816(accR[tm][tx],
                                 (p == 2) ? aL[tm] : aH[tm],
                                 (p == 1) ? bL[tx] : bH[tx]);
            }

            // ======== imag part: sin x Q ========
            #pragma unroll
            for (int tm = 0; tm < 4; ++tm) {
                const char* pH = sm + SM_A(buf, 2) + (tm * 16 + r) * APAD_B + kb;
                const char* pL = sm + SM_A(buf, 3) + (tm * 16 + r) * APAD_B + kb;
                aH[tm][0] = *(const uint32_t*)(pH);
                aH[tm][1] = *(const uint32_t*)(pH + 8 * APAD_B);
                aH[tm][2] = *(const uint32_t*)(pH + 16);
                aH[tm][3] = *(const uint32_t*)(pH + 8 * APAD_B + 16);
                aL[tm][0] = *(const uint32_t*)(pL);
                aL[tm][1] = *(const uint32_t*)(pL + 8 * APAD_B);
                aL[tm][2] = *(const uint32_t*)(pL + 16);
                aL[tm][3] = *(const uint32_t*)(pL + 8 * APAD_B + 16);
            }
            #pragma unroll
            for (int tx = 0; tx < 4; ++tx) {
                const char* pH = sm + SM_B(buf, 2) + (wx + tx * 8 + r) * APAD_B + kb;
                const char* pL = sm + SM_B(buf, 3) + (wx + tx * 8 + r) * APAD_B + kb;
                bH[tx][0] = *(const uint32_t*)(pH);
                bH[tx][1] = *(const uint32_t*)(pH + 16);
                bL[tx][0] = *(const uint32_t*)(pL);
                bL[tx][1] = *(const uint32_t*)(pL + 16);
            }
            #pragma unroll
            for (int p = 0; p < 3; ++p) {
                #pragma unroll
                for (int tm = 0; tm < 4; ++tm)
                    #pragma unroll
                    for (int tx = 0; tx < 4; ++tx)
                        mma16816(accI[tm][tx],
                                 (p == 2) ? aL[tm] : aH[tm],
                                 (p == 1) ? bL[tx] : bH[tx]);
            }
        }
        __syncthreads();
    }

    // ---- epilogue: T = accR - i*accI (+ center row), contract x with Eu ----
    const float* s_img = (const float*)(sm + SM_IMG);
    float pr[4][2], pim[4][2];
    #pragma unroll
    for (int tm = 0; tm < 4; ++tm)
        #pragma unroll
        for (int h = 0; h < 2; ++h) { pr[tm][h] = 0.f; pim[tm][h] = 0.f; }

    #pragma unroll
    for (int tm = 0; tm < 4; ++tm)
        #pragma unroll
        for (int h = 0; h < 2; ++h) {
            int m = tm * 16 + r + h * 8;
            #pragma unroll
            for (int tx = 0; tx < 4; ++tx) {
                int x = wx + tx * 8 + cp * 2;
                float4 e = *(const float4*)(g_Eu + (size_t)(m0 + m) * NPIX + x);
                float tR0 = accR[tm][tx][h * 2 + 0] + s_img[x];
                float tR1 = accR[tm][tx][h * 2 + 1] + s_img[x + 1];
                float tI0 = accI[tm][tx][h * 2 + 0];
                float tI1 = accI[tm][tx][h * 2 + 1];
                pr[tm][h]  = fmaf(tR0, e.x, fmaf(tI0, e.y, fmaf(tR1, e.z, fmaf(tI1, e.w, pr[tm][h]))));
                pim[tm][h] = fmaf(tR0, e.y, fmaf(-tI0, e.x, fmaf(tR1, e.w, fmaf(-tI1, e.z, pim[tm][h]))));
            }
        }
    #pragma unroll
    for (int tm = 0; tm < 4; ++tm)
        #pragma unroll
        for (int h = 0; h < 2; ++h) {
            pr[tm][h]  += __shfl_xor_sync(0xffffffffu, pr[tm][h], 1);
            pr[tm][h]  += __shfl_xor_sync(0xffffffffu, pr[tm][h], 2);
            pim[tm][h] += __shfl_xor_sync(0xffffffffu, pim[tm][h], 1);
            pim[tm][h] += __shfl_xor_sync(0xffffffffu, pim[tm][h], 2);
        }
    float* sredR = (float*)(sm + SM_REDR);
    float* sredI = (float*)(sm + SM_REDI);
    if (cp == 0) {
        #pragma unroll
        for (int tm = 0; tm < 4; ++tm)
            #pragma unroll
            for (int h = 0; h < 2; ++h) {
                int ml = tm * 16 + r + h * 8;
                sredR[warp * 64 + ml] = pr[tm][h];
                sredI[warp * 64 + ml] = pim[tm][h];
            }
    }
    __syncthreads();

    if (tid < 64) {
        float PR = 0.f, PIM = 0.f;
        #pragma unroll
        for (int w = 0; w < 8; ++w) { PR += sredR[w * 64 + tid]; PIM += sredI[w * 64 + tid]; }
        int m = m0 + tid;
        float p0 = pulsefac[m];
        float p1 = pulsefac[M + m];
        float re = PR * p0 - PIM * p1;
        float im = PR * p1 + PIM * p0;
        out[OFF_VIS + (b * 2) * M + m]     = re;
        out[OFF_VIS + (b * 2 + 1) * M + m] = im;
        out[OFF_VISAMP + b * M + m] = sqrtf(re * re + im * im + FEPS);
        g_visR[b * M + m] = re;
        g_visI[b * M + m] = im;
    }
}

// ---------------------------------------------------------------------------
// Kernel 3: merged closures (cphase + logcamp in one launch)
// ---------------------------------------------------------------------------
__global__ void closure_kernel(const float* __restrict__ sign,
                               const int* __restrict__ cpind,
                               const int* __restrict__ caind,
                               float* __restrict__ out) {
    int idx = blockIdx.x * blockDim.x + threadIdx.x;
    if (idx < B * NCP) {
        int b = idx / NCP;
        int n = idx - b * NCP;
        float s = 0.f;
        #pragma unroll
        for (int k = 0; k < 3; ++k) {
            int id   = cpind[k * NCP + n];
            float sg = sign[k * NCP + n];
            s += sg * atan2f(g_visI[b * M + id], g_visR[b * M + id]);
        }
        out[OFF_CPHASE + idx] = s * 57.29577951308232f;
    } else if (idx < B * (NCP + NCA)) {
        int j = idx - B * NCP;
        int b = j / NCA;
        int n = j - b * NCA;
        float la[4];
        #pragma unroll
        for (int k = 0; k < 4; ++k) {
            int id   = caind[k * NCA + n];
            float re = g_visR[b * M + id];
            float im = g_visI[b * M + id];
            la[k] = 0.5f * __logf(re * re + im * im + FEPS);
        }
        out[OFF_LOGCAMP + j] = la[0] + la[1] - la[2] - la[3];
    }
}

extern "C" void kernel_launch(void* const* d_in, const int* in_sizes, int n_in,
                              void* d_out, int out_size) {
    const float* images      = (const float*)d_in[0];
    const float* ktraj       = (const float*)d_in[1];
    const float* pulsefac    = (const float*)d_in[2];
    const float* cphase_sign = (const float*)d_in[3];
    const int*   cphase_ind  = (const int*)d_in[4];
    const int*   camp_ind    = (const int*)d_in[5];
    float* out = (float*)d_out;

    cudaFuncSetAttribute(dft_mma_kernel, cudaFuncAttributeMaxDynamicSharedMemorySize, SM_TOTAL);

    trig_kernel<<<M, 128>>>(ktraj);
    fold_kernel<<<(B * NPIX * KFOLD) / 256, 256>>>(images);

    dim3 grid(M / MTILE, B);
    dft_mma_kernel<<<grid, 256, SM_TOTAL>>>(images, pulsefac, out);

    closure_kernel<<<(B * (NCP + NCA) + 255) / 256, 256>>>(cphase_sign, cphase_ind, camp_ind, out);
}

// round 14
// speedup vs baseline: 2.5999x; 1.0154x over previous
#include <cuda_runtime.h>
#include <cuda_bf16.h>
#include <cstdint>
#include <math.h>

#define B 8
#define NPIX 256
#define M 8192
#define NCP 24576
#define NCA 24576
#define FEPS 1e-16f
#define KFOLD 128
#define MTILE 64

#define OFF_VIS 0
#define OFF_VISAMP (B*2*M)
#define OFF_CPHASE (OFF_VISAMP + B*M)
#define OFF_LOGCAMP (OFF_CPHASE + B*NCP)

#define NCHUNK 12
#define CP_CHUNK (NCP / NCHUNK)   // 2048
#define CA_CHUNK (NCA / NCHUNK)   // 2048

// ---- device scratch (no allocation allowed) ----
__device__ __nv_bfloat16 g_cosHi[M*KFOLD];    // [m][c], c fastest
__device__ __nv_bfloat16 g_cosLo[M*KFOLD];
__device__ __nv_bfloat16 g_sinHi[M*KFOLD];
__device__ __nv_bfloat16 g_sinLo[M*KFOLD];
__device__ float2        g_Eu[M*NPIX];        // [m][x]  (er, ei)
__device__ __nv_bfloat16 g_PHi[B*NPIX*KFOLD]; // [b][x][c], c fastest
__device__ __nv_bfloat16 g_PLo[B*NPIX*KFOLD];
__device__ __nv_bfloat16 g_QHi[B*NPIX*KFOLD];
__device__ __nv_bfloat16 g_QLo[B*NPIX*KFOLD];
__device__ float2 g_vis2[B*M];                // packed (re, im)

// ---------------------------------------------------------------------------
// m16n8k16 bf16 mma (baseline PTX, no arch-suffix gating -> ok on sm_103)
// ---------------------------------------------------------------------------
__device__ __forceinline__ void mma16816(float* d, const uint32_t* a, const uint32_t* b) {
    asm volatile(
        "mma.sync.aligned.m16n8k16.row.col.f32.bf16.bf16.f32 "
        "{%0,%1,%2,%3}, {%4,%5,%6,%7}, {%8,%9}, {%0,%1,%2,%3};"
        : "+f"(d[0]), "+f"(d[1]), "+f"(d[2]), "+f"(d[3])
        : "r"(a[0]), "r"(a[1]), "r"(a[2]), "r"(a[3]), "r"(b[0]), "r"(b[1]));
}
__device__ __forceinline__ uint32_t smem_u32(const void* p) {
    uint32_t a;
    asm("{ .reg .u64 t; cvta.to.shared.u64 t, %1; cvt.u32.u64 %0, t; }" : "=r"(a) : "l"(p));
    return a;
}
__device__ __forceinline__ void cp_async16(uint32_t dst, const void* src) {
    asm volatile("cp.async.cg.shared.global [%0], [%1], 16;" :: "r"(dst), "l"(src));
}
#define CP_COMMIT()  asm volatile("cp.async.commit_group;" ::: "memory")
#define CP_WAIT1()   asm volatile("cp.async.wait_group 1;" ::: "memory")
#define CP_WAIT0()   asm volatile("cp.async.wait_group 0;" ::: "memory")

// ---------------- SMEM layout (dft kernel) ----------------
#define APAD_B   80
#define A_ARR_B  (64 * APAD_B)      // 5120
#define B_ARR_B  (256 * APAD_B)     // 20480
#define STAGE_B  (4 * A_ARR_B + 4 * B_ARR_B)   // 102400 per buffer
#define SM_A(buf, arr)  ((buf) * STAGE_B + (arr) * A_ARR_B)
#define SM_B(buf, arr)  ((buf) * STAGE_B + 4 * A_ARR_B + (arr) * B_ARR_B)
#define SM_IMG      (2 * STAGE_B)
#define SM_REDR     (SM_IMG + 1024)
#define SM_REDI     (SM_REDR + 2048)
#define SM_TOTAL    (SM_REDI + 2048)                     // 209920

// ---------------------------------------------------------------------------
// Kernel 1: merged trig + fold.  Blocks [0, M): trig for m = blockIdx.x
// (validated anchor-decomposition math from R12/R13).  Blocks [M, M+2048):
// fold (idx = (blockIdx.x - M)*128 + tid).
// ---------------------------------------------------------------------------
__global__ __launch_bounds__(128) void trig_fold_kernel(
    const float* __restrict__ ktraj,
    const float* __restrict__ img)
{
    const int lid = threadIdx.x;          // 0..127
    if (blockIdx.x < M) {
        __shared__ float sc[65], ss[65], sr[65];
        const int m = blockIdx.x;
        const float kv = ktraj[m];
        const float ku = ktraj[M + m];

        if (lid < 65) {
            float base, k;
            if (lid < 17)      { base = (float)(8 * lid);             k = kv; }
            else if (lid < 25) { base = (float)(lid - 17);            k = kv; }
            else if (lid < 57) { base = (float)(8 * (lid - 25 - 16)); k = ku; }
            else               { base = (float)(lid - 57);            k = ku; }
            float a = k * base;
            float r = fmaf(k, base, -a);   // exact: k*base = a + r
            float s, c;
            sincosf(a, &s, &c);
            sc[lid] = c; ss[lid] = s; sr[lid] = r;
        }
        __syncthreads();

        {                                  // A tables: c' = lid+1 in [1,128]
            int cc = lid + 1;
            int j = cc >> 3, l = cc & 7;
            float cf  = (float)cc;
            float th  = kv * cf;
            float rth = fmaf(kv, cf, -th);
            float d   = sr[j] + sr[17 + l] - rth;
            float C = sc[j] * sc[17 + l] - ss[j] * ss[17 + l];
            float S = ss[j] * sc[17 + l] + sc[j] * ss[17 + l];
            float Cc = fmaf(-d, S, C);
            float Sc = fmaf( d, C, S);
            __nv_bfloat16 ch = __float2bfloat16(Cc);
            __nv_bfloat16 sh = __float2bfloat16(Sc);
            int o = m * KFOLD + lid;
            g_cosHi[o] = ch;
            g_cosLo[o] = __float2bfloat16(Cc - __bfloat162float(ch));
            g_sinHi[o] = sh;
            g_sinLo[o] = __float2bfloat16(Sc - __bfloat162float(sh));
        }
        #pragma unroll
        for (int xx = 0; xx < 2; ++xx) {   // Eu: x = lid and lid+128
            int x = lid + xx * 128;
            int j = x >> 3, l = x & 7;
            float cxf = (float)(x - 128);
            float th  = ku * cxf;
            float rth = fmaf(ku, cxf, -th);
            float d   = sr[25 + j] + sr[57 + l] - rth;
            float C = sc[25 + j] * sc[57 + l] - ss[25 + j] * ss[57 + l];
            float S = ss[25 + j] * sc[57 + l] + sc[25 + j] * ss[57 + l];
            float Cc = fmaf(-d, S, C);
            float Sc = fmaf( d, C, S);
            g_Eu[m * NPIX + x] = make_float2(Cc, -Sc);
        }
    } else {
        // fold: idx over B*NPIX*KFOLD = 262144 = 2048 blocks * 128 threads
        int idx = (blockIdx.x - M) * 128 + lid;
        int c = idx & (KFOLD - 1);
        int x = (idx >> 7) & (NPIX - 1);
        int b = idx >> 15;
        int cc = c + 1;
        const float* im = img + (size_t)b * NPIX * NPIX;
        float p, q;
        if (cc < 128) {
            float hi = im[(128 + cc) * NPIX + x];
            float lo = im[(128 - cc) * NPIX + x];
            p = hi + lo; q = hi - lo;
        } else {
            float v = im[x];
            p = v; q = -v;
        }
        __nv_bfloat16 ph = __float2bfloat16(p);
        __nv_bfloat16 qh = __float2bfloat16(q);
        g_PHi[idx] = ph;
        g_PLo[idx] = __float2bfloat16(p - __bfloat162float(ph));
        g_QHi[idx] = qh;
        g_QLo[idx] = __float2bfloat16(q - __bfloat162float(qh));
    }
}

// ---------------------------------------------------------------------------
// Kernel 2: HMMA stage (byte-identical mainloop to validated R13).
// ---------------------------------------------------------------------------
__global__ __launch_bounds__(256, 1) void dft_mma_kernel(
    const float* __restrict__ img,
    const float* __restrict__ pulsefac,
    float* __restrict__ out)
{
    extern __shared__ char sm[];
    const uint32_t smb = smem_u32(sm);

    const int b    = blockIdx.y;
    const int m0   = blockIdx.x * MTILE;
    const int tid  = threadIdx.x;
    const int warp = tid >> 5;
    const int lane = tid & 31;
    const int r    = lane >> 2;
    const int cp   = lane & 3;
    const int wx   = warp * 32;

    float accR[4][4][4], accI[4][4][4];
    #pragma unroll
    for (int i = 0; i < 4; ++i)
        #pragma unroll
        for (int j = 0; j < 4; ++j)
            #pragma unroll
            for (int k = 0; k < 4; ++k) { accR[i][j][k] = 0.f; accI[i][j][k] = 0.f; }

    ((float*)(sm + SM_IMG))[tid] = img[((size_t)b * NPIX + 128) * NPIX + tid];

    const __nv_bfloat16* gA[4] = {g_cosHi, g_cosLo, g_sinHi, g_sinLo};
    const __nv_bfloat16* gB[4] = {g_PHi, g_PLo, g_QHi, g_QLo};

    auto stage = [&](int buf, int chunk) {
        const int c0 = chunk * 32;
        #pragma unroll
        for (int t = tid; t < 1024; t += 256) {
            int arr = t >> 8, rem = t & 255, row = rem >> 2, seg = rem & 3;
            cp_async16(smb + SM_A(buf, arr) + row * APAD_B + seg * 16,
                       gA[arr] + ((size_t)(m0 + row)) * KFOLD + c0 + seg * 8);
        }
        #pragma unroll
        for (int t = tid; t < 4096; t += 256) {
            int arr = t >> 10, rem = t & 1023, row = rem >> 2, seg = rem & 3;
            cp_async16(smb + SM_B(buf, arr) + row * APAD_B + seg * 16,
                       gB[arr] + ((size_t)(b * NPIX + row)) * KFOLD + c0 + seg * 8);
        }
    };

    stage(0, 0);
    CP_COMMIT();

    for (int chunk = 0; chunk < 4; ++chunk) {
        const int buf = chunk & 1;
        if (chunk < 3) { stage(buf ^ 1, chunk + 1); CP_COMMIT(); }
        if (chunk < 3) CP_WAIT1(); else CP_WAIT0();
        __syncthreads();

        #pragma unroll
        for (int ks = 0; ks < 2; ++ks) {
            const int kb = ks * 32 + cp * 4;
            uint32_t aH[4][4], aL[4][4], bH[4][2], bL[4][2];

            // ======== real part: cos x P ========
            #pragma unroll
            for (int tm = 0; tm < 4; ++tm) {
                const char* pH = sm + SM_A(buf, 0) + (tm * 16 + r) * APAD_B + kb;
                const char* pL = sm + SM_A(buf, 1) + (tm * 16 + r) * APAD_B + kb;
                aH[tm][0] = *(const uint32_t*)(pH);
                aH[tm][1] = *(const uint32_t*)(pH + 8 * APAD_B);
                aH[tm][2] = *(const uint32_t*)(pH + 16);
                aH[tm][3] = *(const uint32_t*)(pH + 8 * APAD_B + 16);
                aL[tm][0] = *(const uint32_t*)(pL);
                aL[tm][1] = *(const uint32_t*)(pL + 8 * APAD_B);
                aL[tm][2] = *(const uint32_t*)(pL + 16);
                aL[tm][3] = *(const uint32_t*)(pL + 8 * APAD_B + 16);
            }
            #pragma unroll
            for (int tx = 0; tx < 4; ++tx) {
                const char* pH = sm + SM_B(buf, 0) + (wx + tx * 8 + r) * APAD_B + kb;
                const char* pL = sm + SM_B(buf, 1) + (wx + tx * 8 + r) * APAD_B + kb;
                bH[tx][0] = *(const uint32_t*)(pH);
                bH[tx][1] = *(const uint32_t*)(pH + 16);
                bL[tx][0] = *(const uint32_t*)(pL);
                bL[tx][1] = *(const uint32_t*)(pL + 16);
            }
            #pragma unroll
            for (int p = 0; p < 3; ++p) {
                #pragma unroll
                for (int tm = 0; tm < 4; ++tm)
                    #pragma unroll
                    for (int tx = 0; tx < 4; ++tx)
                        mma16816(accR[tm][tx],
                                 (p == 2) ? aL[tm] : aH[tm],
                                 (p == 1) ? bL[tx] : bH[tx]);
            }

            // ======== imag part: sin x Q ========
            #pragma unroll
            for (int tm = 0; tm < 4; ++tm) {
                const char* pH = sm + SM_A(buf, 2) + (tm * 16 + r) * APAD_B + kb;
                const char* pL = sm + SM_A(buf, 3) + (tm * 16 + r) * APAD_B + kb;
                aH[tm][0] = *(const uint32_t*)(pH);
                aH[tm][1] = *(const uint32_t*)(pH + 8 * APAD_B);
                aH[tm][2] = *(const uint32_t*)(pH + 16);
                aH[tm][3] = *(const uint32_t*)(pH + 8 * APAD_B + 16);
                aL[tm][0] = *(const uint32_t*)(pL);
                aL[tm][1] = *(const uint32_t*)(pL + 8 * APAD_B);
                aL[tm][2] = *(const uint32_t*)(pL + 16);
                aL[tm][3] = *(const uint32_t*)(pL + 8 * APAD_B + 16);
            }
            #pragma unroll
            for (int tx = 0; tx < 4; ++tx) {
                const char* pH = sm + SM_B(buf, 2) + (wx + tx * 8 + r) * APAD_B + kb;
                const char* pL = sm + SM_B(buf, 3) + (wx + tx * 8 + r) * APAD_B + kb;
                bH[tx][0] = *(const uint32_t*)(pH);
                bH[tx][1] = *(const uint32_t*)(pH + 16);
                bL[tx][0] = *(const uint32_t*)(pL);
                bL[tx][1] = *(const uint32_t*)(pL + 16);
            }
            #pragma unroll
            for (int p = 0; p < 3; ++p) {
                #pragma unroll
                for (int tm = 0; tm < 4; ++tm)
                    #pragma unroll
                    for (int tx = 0; tx < 4; ++tx)
                        mma16816(accI[tm][tx],
                                 (p == 2) ? aL[tm] : aH[tm],
                                 (p == 1) ? bL[tx] : bH[tx]);
            }
        }
        __syncthreads();
    }

    // ---- epilogue: T = accR - i*accI (+ center row), contract x with Eu ----
    const float* s_img = (const float*)(sm + SM_IMG);
    float pr[4][2], pim[4][2];
    #pragma unroll
    for (int tm = 0; tm < 4; ++tm)
        #pragma unroll
        for (int h = 0; h < 2; ++h) { pr[tm][h] = 0.f; pim[tm][h] = 0.f; }

    #pragma unroll
    for (int tm = 0; tm < 4; ++tm)
        #pragma unroll
        for (int h = 0; h < 2; ++h) {
            int m = tm * 16 + r + h * 8;
            #pragma unroll
            for (int tx = 0; tx < 4; ++tx) {
                int x = wx + tx * 8 + cp * 2;
                float4 e = *(const float4*)(g_Eu + (size_t)(m0 + m) * NPIX + x);
                float tR0 = accR[tm][tx][h * 2 + 0] + s_img[x];
                float tR1 = accR[tm][tx][h * 2 + 1] + s_img[x + 1];
                float tI0 = accI[tm][tx][h * 2 + 0];
                float tI1 = accI[tm][tx][h * 2 + 1];
                pr[tm][h]  = fmaf(tR0, e.x, fmaf(tI0, e.y, fmaf(tR1, e.z, fmaf(tI1, e.w, pr[tm][h]))));
                pim[tm][h] = fmaf(tR0, e.y, fmaf(-tI0, e.x, fmaf(tR1, e.w, fmaf(-tI1, e.z, pim[tm][h]))));
            }
        }
    #pragma unroll
    for (int tm = 0; tm < 4; ++tm)
        #pragma unroll
        for (int h = 0; h < 2; ++h) {
            pr[tm][h]  += __shfl_xor_sync(0xffffffffu, pr[tm][h], 1);
            pr[tm][h]  += __shfl_xor_sync(0xffffffffu, pr[tm][h], 2);
            pim[tm][h] += __shfl_xor_sync(0xffffffffu, pim[tm][h], 1);
            pim[tm][h] += __shfl_xor_sync(0xffffffffu, pim[tm][h], 2);
        }
    float* sredR = (float*)(sm + SM_REDR);
    float* sredI = (float*)(sm + SM_REDI);
    if (cp == 0) {
        #pragma unroll
        for (int tm = 0; tm < 4; ++tm)
            #pragma unroll
            for (int h = 0; h < 2; ++h) {
                int ml = tm * 16 + r + h * 8;
                sredR[warp * 64 + ml] = pr[tm][h];
                sredI[warp * 64 + ml] = pim[tm][h];
            }
    }
    __syncthreads();

    if (tid < 64) {
        float PR = 0.f, PIM = 0.f;
        #pragma unroll
        for (int w = 0; w < 8; ++w) { PR += sredR[w * 64 + tid]; PIM += sredI[w * 64 + tid]; }
        int m = m0 + tid;
        float p0 = pulsefac[m];
        float p1 = pulsefac[M + m];
        float re = PR * p0 - PIM * p1;
        float im = PR * p1 + PIM * p0;
        out[OFF_VIS + (b * 2) * M + m]     = re;
        out[OFF_VIS + (b * 2 + 1) * M + m] = im;
        out[OFF_VISAMP + b * M + m] = sqrtf(re * re + im * im + FEPS);
        g_vis2[b * M + m] = make_float2(re, im);
    }
}

// ---------------------------------------------------------------------------
// Kernel 3: closures with per-b vis table staged in smem (64 KB).
// Block = (chunk, b).  Gathers hit smem (29 cyc) instead of L2 (~234 cyc).
// ---------------------------------------------------------------------------
__global__ __launch_bounds__(256) void closure_kernel(
    const float* __restrict__ sign,
    const int* __restrict__ cpind,
    const int* __restrict__ caind,
    float* __restrict__ out)
{
    extern __shared__ float2 svis[];   // M float2 = 64 KB
    const int chunk = blockIdx.x;
    const int b     = blockIdx.y;
    const int tid   = threadIdx.x;

    // stage vis table for this b (vectorized float4 = 2 float2 per load)
    {
        const float4* src = (const float4*)(g_vis2 + (size_t)b * M);
        float4* dst = (float4*)svis;
        #pragma unroll
        for (int t = tid; t < M / 2; t += 256) dst[t] = src[t];
    }
    __syncthreads();

    // cphase chunk
    #pragma unroll
    for (int i = 0; i < CP_CHUNK / 256; ++i) {
        int n = chunk * CP_CHUNK + i * 256 + tid;
        float s = 0.f;
        #pragma unroll
        for (int k = 0; k < 3; ++k) {
            int id   = cpind[k * NCP + n];
            float sg = sign[k * NCP + n];
            float2 v = svis[id];
            s += sg * atan2f(v.y, v.x);
        }
        out[OFF_CPHASE + b * NCP + n] = s * 57.29577951308232f;
    }
    // logcamp chunk
    #pragma unroll
    for (int i = 0; i < CA_CHUNK / 256; ++i) {
        int n = chunk * CA_CHUNK + i * 256 + tid;
        float la[4];
        #pragma unroll
        for (int k = 0; k < 4; ++k) {
            int id   = caind[k * NCA + n];
            float2 v = svis[id];
            la[k] = 0.5f * __logf(v.x * v.x + v.y * v.y + FEPS);
        }
        out[OFF_LOGCAMP + b * NCA + n] = la[0] + la[1] - la[2] - la[3];
    }
}

extern "C" void kernel_launch(void* const* d_in, const int* in_sizes, int n_in,
                              void* d_out, int out_size) {
    const float* images      = (const float*)d_in[0];
    const float* ktraj       = (const float*)d_in[1];
    const float* pulsefac    = (const float*)d_in[2];
    const float* cphase_sign = (const float*)d_in[3];
    const int*   cphase_ind  = (const int*)d_in[4];
    const int*   camp_ind    = (const int*)d_in[5];
    float* out = (float*)d_out;

    cudaFuncSetAttribute(dft_mma_kernel, cudaFuncAttributeMaxDynamicSharedMemorySize, SM_TOTAL);
    cudaFuncSetAttribute(closure_kernel, cudaFuncAttributeMaxDynamicSharedMemorySize, M * sizeof(float2));

    trig_fold_kernel<<<M + (B * NPIX * KFOLD) / 128, 128>>>(ktraj, images);

    dim3 grid(M / MTILE, B);
    dft_mma_kernel<<<grid, 256, SM_TOTAL>>>(images, pulsefac, out);

    dim3 cgrid(NCHUNK, B);
    closure_kernel<<<cgrid, 256, M * sizeof(float2)>>>(cphase_sign, cphase_ind, camp_ind, out);
}